// round 10
// baseline (speedup 1.0000x reference)
#include <cuda_runtime.h>
#include <cuda_bf16.h>
#include <cstdint>
#include <math.h>

// Problem constants
#define BATCH 2
#define SEQ   4096
#define HID   2048
#define DK    128
#define CHUNK 64
#define NCHUNK 64                  // per batch
#define NCC   (BATCH*NCHUNK)       // 128 total batch-chunks
#define NTOK  (BATCH*SEQ)          // 8192

// ---------------- fp32 scratch ------------------------------------------------
__device__ float g_sq[(size_t)NTOK*DK];         // q scores -> q (softmax)
__device__ float g_sk[(size_t)NTOK*DK];         // k scores -> k (sigmoid)
__device__ float g_QE[(size_t)NCC*CHUNK*DK];    // q * exp(B - Bm)
__device__ float g_KE[(size_t)NCC*CHUNK*DK];    // k * exp(Bm - B)
__device__ float g_qb[(size_t)NCC*CHUNK*DK];    // q * exp(B)
__device__ float g_kd[(size_t)NCC*CHUNK*DK];    // k * exp(Blast - B)
__device__ float g_el[NCC*DK];                  // exp(Blast)
__device__ float g_A [(size_t)NCC*CHUNK*CHUNK]; // tril intra matrices
__device__ float g_T [(size_t)NCC*DK*HID];      // T_c then (in-place) S_before_c
__device__ float g_o [(size_t)NTOK*HID];        // attention output o (fp32)
__device__ float g_G [(size_t)NTOK*HID];        // gate scores

// ---------------- int8 two-level quant scratch ---------------------------------
__device__ __align__(16) int8_t g_x0 [(size_t)NTOK*HID];
__device__ __align__(16) int8_t g_x1 [(size_t)NTOK*HID];
__device__ float g_sx [NTOK];
__device__ __align__(16) int8_t g_wq0[(size_t)DK*HID];
__device__ __align__(16) int8_t g_wq1[(size_t)DK*HID];
__device__ float g_swq[DK];
__device__ __align__(16) int8_t g_wk0[(size_t)DK*HID];
__device__ __align__(16) int8_t g_wk1[(size_t)DK*HID];
__device__ float g_swk[DK];
__device__ __align__(16) int8_t g_wog0[(size_t)HID*HID];
__device__ __align__(16) int8_t g_wog1[(size_t)HID*HID];
__device__ float g_swog[HID];
__device__ __align__(16) int8_t g_wig0[(size_t)HID*HID];
__device__ __align__(16) int8_t g_wig1[(size_t)HID*HID];
__device__ float g_swig[HID];
__device__ __align__(16) int8_t g_wo0[(size_t)HID*HID];
__device__ __align__(16) int8_t g_wo1[(size_t)HID*HID];
__device__ float g_swo[HID];
__device__ __align__(16) int8_t g_o0 [(size_t)NTOK*HID];
__device__ __align__(16) int8_t g_o1 [(size_t)NTOK*HID];
__device__ float g_so [NTOK];
__device__ __align__(16) int8_t g_t0 [(size_t)NTOK*HID];
__device__ __align__(16) int8_t g_t1 [(size_t)NTOK*HID];
__device__ float g_st [NTOK];

// ---------------- helpers -----------------------------------------------------
__device__ __forceinline__ uint32_t smem_u32(const void* p) {
    uint32_t a;
    asm("{ .reg .u64 t; cvta.to.shared.u64 t, %1; cvt.u32.u64 %0, t; }" : "=r"(a) : "l"(p));
    return a;
}
#define CPASYNC16(dst, src) \
    asm volatile("cp.async.cg.shared.global [%0], [%1], 16;" :: "r"(dst), "l"(src) : "memory")
#define CPCOMMIT() asm volatile("cp.async.commit_group;" ::: "memory")
#define CPWAIT1()  asm volatile("cp.async.wait_group 1;" ::: "memory")
#define CPWAIT0()  asm volatile("cp.async.wait_group 0;" ::: "memory")
#define LDSM4(r0, r1, r2, r3, addr) \
    asm volatile("ldmatrix.sync.aligned.m8n8.x4.shared.b16 {%0,%1,%2,%3}, [%4];" \
        : "=r"(r0), "=r"(r1), "=r"(r2), "=r"(r3) : "r"(addr))

__device__ __forceinline__ void mma_s8(int* c, const uint32_t* a, const uint32_t* b) {
    asm volatile(
        "mma.sync.aligned.m16n8k32.row.col.s32.s8.s8.s32 "
        "{%0,%1,%2,%3}, {%4,%5,%6,%7}, {%8,%9}, {%0,%1,%2,%3};"
        : "+r"(c[0]), "+r"(c[1]), "+r"(c[2]), "+r"(c[3])
        : "r"(a[0]), "r"(a[1]), "r"(a[2]), "r"(a[3]), "r"(b[0]), "r"(b[1]));
}

// two-level int8 encode: t = 127*v/amax; q0 = rn(t); q1 = rn(128*(t-q0)).
// ALL float->int8 conversions go through __float2int_rn then int8_t:
// plain (char) is UNSIGNED on aarch64 and clamps negatives to 0 in PTX cvt.
__device__ __forceinline__ void enc2(float t, int8_t& a, int8_t& b) {
    int q0 = __float2int_rn(t);
    int q1 = __float2int_rn(128.f * (t - (float)q0));
    a = (int8_t)q0;
    b = (int8_t)q1;
}

// ---------------- per-row two-level int8 quantization --------------------------
// Rows of 2048 floats; up to 3 tensors per launch (blockIdx.y selects).
__global__ __launch_bounds__(256) void quant_rows(
    const float* __restrict__ s0p, int8_t* q00, int8_t* q01, float* sc0,
    const float* __restrict__ s1p, int8_t* q10, int8_t* q11, float* sc1,
    const float* __restrict__ s2p, int8_t* q20, int8_t* q21, float* sc2)
{
    const float* src; int8_t *q0, *q1; float* sc;
    if (blockIdx.y == 0)      { src = s0p; q0 = q00; q1 = q01; sc = sc0; }
    else if (blockIdx.y == 1) { src = s1p; q0 = q10; q1 = q11; sc = sc1; }
    else                      { src = s2p; q0 = q20; q1 = q21; sc = sc2; }
    int row = blockIdx.x, tid = threadIdx.x;
    int lane = tid & 31, w = tid >> 5;
    const float4* r4 = (const float4*)(src + (size_t)row * HID);
    float4 v0 = r4[tid], v1 = r4[tid + 256];
    float m = fmaxf(fmaxf(fmaxf(fabsf(v0.x), fabsf(v0.y)), fmaxf(fabsf(v0.z), fabsf(v0.w))),
                    fmaxf(fmaxf(fabsf(v1.x), fabsf(v1.y)), fmaxf(fabsf(v1.z), fabsf(v1.w))));
#pragma unroll
    for (int o = 16; o; o >>= 1) m = fmaxf(m, __shfl_xor_sync(0xffffffffu, m, o));
    __shared__ float red[8];
    if (!lane) red[w] = m;
    __syncthreads();
    float amax = red[0];
#pragma unroll
    for (int i = 1; i < 8; i++) amax = fmaxf(amax, red[i]);
    float s = (amax > 0.f) ? amax : 1.f;
    if (tid == 0) sc[row] = s * (1.f / 127.f);
    float inv = 127.f / s;

    int8_t a0[8], a1[8];
    enc2(v0.x * inv, a0[0], a1[0]); enc2(v0.y * inv, a0[1], a1[1]);
    enc2(v0.z * inv, a0[2], a1[2]); enc2(v0.w * inv, a0[3], a1[3]);
    enc2(v1.x * inv, a0[4], a1[4]); enc2(v1.y * inv, a0[5], a1[5]);
    enc2(v1.z * inv, a0[6], a1[6]); enc2(v1.w * inv, a0[7], a1[7]);

    size_t base = (size_t)row * HID;
    *(char4*)(q0 + base + tid * 4)        = make_char4(a0[0], a0[1], a0[2], a0[3]);
    *(char4*)(q0 + base + 1024 + tid * 4) = make_char4(a0[4], a0[5], a0[6], a0[7]);
    *(char4*)(q1 + base + tid * 4)        = make_char4(a1[0], a1[1], a1[2], a1[3]);
    *(char4*)(q1 + base + 1024 + tid * 4) = make_char4(a1[4], a1[5], a1[6], a1[7]);
}

// ============ int8 mma.sync GEMM segment: C (+)= w*sa_i*sb_j * sum_ph A@B^T ====
// CTA 128x128, 8 warps (2x4), warp 64x32. K-chunk 128 int8 (128B rows, same smem
// geometry as the proven bf16 version). 3-stage cp.async pipeline, 1 barrier per
// chunk. nph<=2 phases share the s32 accumulators; epilogue folds to float C with
// weight wsc*sa[row]*sb[col] (accum=0 write / 1 read-modify-write).
// zsplit: blockIdx.z==1 swaps (B,C,sb) -> (Bz,Cz,sbz) [q/k fusion].
#define PITCHB 144
#define TILEB (128 * PITCHB)       // 18432
#define STAGEB (2 * TILEB)         // 36864
#define NSTG 3
#define GSMEM (NSTG * STAGEB)      // 110592

__global__ void __launch_bounds__(256, 2) im_gemm(
    const int8_t* __restrict__ Aa, const int8_t* __restrict__ Ab,
    const int8_t* __restrict__ Ba, const int8_t* __restrict__ Bb,
    float* __restrict__ C, const float* __restrict__ sa, const float* __restrict__ sb,
    const int8_t* __restrict__ Bza, const int8_t* __restrict__ Bzb,
    float* __restrict__ Cz, const float* __restrict__ sbz,
    float wsc, int accum, int nph, int zsplit, int K, int Ncols)
{
    extern __shared__ char smc[];
    const int tid = threadIdx.x, lane = tid & 31, wid = tid >> 5;
    const int wm = wid & 1, wn = wid >> 1;
    const int r = lane >> 2, kq = lane & 3;
    const long bm = (long)blockIdx.y * 128;
    const long bn = (long)blockIdx.x * 128;

    if (zsplit && blockIdx.z) { Ba = Bza; Bb = Bzb; C = Cz; sb = sbz; }
    const int kpc = K >> 7;              // 128-wide chunks per phase
    const int nT = nph * kpc;

    int acc[4][4][4];
#pragma unroll
    for (int i = 0; i < 4; i++)
#pragma unroll
        for (int j = 0; j < 4; j++)
#pragma unroll
            for (int t = 0; t < 4; t++) acc[i][j][t] = 0;

    const uint32_t sb32 = smem_u32(smc);

    auto issue = [&](int t, int stg) {
        const int8_t* Ap = (t >= kpc) ? Ab : Aa;
        const int8_t* Bp = (t >= kpc) ? Bb : Ba;
        int k0 = ((t >= kpc) ? (t - kpc) : t) << 7;
        uint32_t As = sb32 + stg * STAGEB;
        uint32_t Bs = As + TILEB;
#pragma unroll
        for (int i = 0; i < 4; i++) {
            int u = tid + i * 256;
            int row = u >> 3, s = u & 7;
            CPASYNC16(As + row * PITCHB + s * 16, Ap + (bm + row) * (long)K + k0 + s * 16);
            CPASYNC16(Bs + row * PITCHB + s * 16, Bp + (bn + row) * (long)K + k0 + s * 16);
        }
        CPCOMMIT();
    };

    // ldmatrix per-lane byte offsets (s8-k32 fragments are byte-identical to
    // the f16-k16 fragments this addressing produced in the passing bf16 kernel)
    const int lm = lane >> 3, li = lane & 7;
    uint32_t aoff[4], boff[2];
#pragma unroll
    for (int mt = 0; mt < 4; mt++) {
        int arow = wm * 64 + mt * 16 + (lm & 1) * 8 + li;
        aoff[mt] = (uint32_t)(arow * PITCHB + (lm >> 1) * 16);
    }
#pragma unroll
    for (int p = 0; p < 2; p++) {
        int nt = 2 * p + (lm >> 1);
        int brow = wn * 32 + nt * 8 + li;
        boff[p] = (uint32_t)(brow * PITCHB + (lm & 1) * 16);
    }

    issue(0, 0);
    issue(1, 1);

    int st = 0, ist = 2;
    for (int t = 0; t < nT; t++) {
        if (t == nT - 1) CPWAIT0(); else CPWAIT1();
        __syncthreads();
        if (t + 2 < nT) issue(t + 2, ist);
        uint32_t As = sb32 + st * STAGEB;
        uint32_t Bs = As + TILEB;
#pragma unroll
        for (int ks = 0; ks < 4; ks++) {
            uint32_t af[4][4], bfr[2][4];
#pragma unroll
            for (int mt = 0; mt < 4; mt++)
                LDSM4(af[mt][0], af[mt][1], af[mt][2], af[mt][3], As + aoff[mt] + ks * 32);
#pragma unroll
            for (int p = 0; p < 2; p++)
                LDSM4(bfr[p][0], bfr[p][1], bfr[p][2], bfr[p][3], Bs + boff[p] + ks * 32);
#pragma unroll
            for (int mt = 0; mt < 4; mt++) {
                mma_s8(acc[mt][0], af[mt], &bfr[0][0]);
                mma_s8(acc[mt][1], af[mt], &bfr[0][2]);
                mma_s8(acc[mt][2], af[mt], &bfr[1][0]);
                mma_s8(acc[mt][3], af[mt], &bfr[1][2]);
            }
        }
        st = (st == NSTG - 1) ? 0 : st + 1;
        ist = (ist == NSTG - 1) ? 0 : ist + 1;
    }

    // epilogue: C (+)= wsc * sa[row] * sb[col] * acc
#pragma unroll
    for (int mt = 0; mt < 4; mt++) {
        long row0 = bm + wm * 64 + mt * 16 + r;
        float sa0 = wsc * __ldg(&sa[row0]);
        float sa1 = wsc * __ldg(&sa[row0 + 8]);
#pragma unroll
        for (int nt = 0; nt < 4; nt++) {
            long col = bn + wn * 32 + nt * 8 + kq * 2;
            float sb0 = __ldg(&sb[col]), sb1 = __ldg(&sb[col + 1]);
            float2 v0 = make_float2(sa0 * sb0 * (float)acc[mt][nt][0],
                                    sa0 * sb1 * (float)acc[mt][nt][1]);
            float2 v1 = make_float2(sa1 * sb0 * (float)acc[mt][nt][2],
                                    sa1 * sb1 * (float)acc[mt][nt][3]);
            float* p0 = &C[row0 * (long)Ncols + col];
            float* p1 = &C[(row0 + 8) * (long)Ncols + col];
            if (accum) {
                float2 o0 = *(float2*)p0, o1 = *(float2*)p1;
                v0.x += o0.x; v0.y += o0.y; v1.x += o1.x; v1.y += o1.y;
            }
            *(float2*)p0 = v0;
            *(float2*)p1 = v1;
        }
    }
}

// ---------------- q softmax / k sigmoid (in-place on score buffers) -----------
__global__ void qk_act(float* __restrict__ sq, float* __restrict__ sk)
{
    int t = blockIdx.x, d = threadIdx.x;            // 128 threads
    int lane = d & 31, w = d >> 5;
    __shared__ float sm[4], ss[4];
    size_t idx = (size_t)t * DK + d;
    float v = sq[idx];
    float m = v;
#pragma unroll
    for (int o = 16; o; o >>= 1) m = fmaxf(m, __shfl_xor_sync(0xffffffffu, m, o));
    if (!lane) sm[w] = m;
    __syncthreads();
    m = fmaxf(fmaxf(sm[0], sm[1]), fmaxf(sm[2], sm[3]));
    float e = expf(v - m);
    float s = e;
#pragma unroll
    for (int o = 16; o; o >>= 1) s += __shfl_xor_sync(0xffffffffu, s, o);
    if (!lane) ss[w] = s;
    __syncthreads();
    s = ss[0] + ss[1] + ss[2] + ss[3];
    sq[idx] = e / s;
    float kv = sk[idx];
    sk[idx] = 1.f / (1.f + expf(-kv));
}

// ---------------- per-chunk decay prep (product form) -------------------------
__global__ void chunk_prep(const float* __restrict__ q, const float* __restrict__ k)
{
    int cc = blockIdx.x;
    int d = threadIdx.x;                 // 128 threads
    __shared__ float us[CHUNK][DK];
    size_t base = (size_t)cc * CHUNK * DK + d;
    float P = 1.f;
#pragma unroll 4
    for (int i = 0; i < CHUNK; i++) {
        float kv = k[base + (size_t)i * DK];
        float u = 1.f / (1.f + expf(kv));
        us[i][d] = u;
        P *= u;
    }
    float Pl = P;
    float invs = rsqrtf(Pl);
    float sq_ = sqrtf(Pl);
    P = 1.f;
#pragma unroll 4
    for (int i = 0; i < CHUNK; i++) {
        size_t idx = base + (size_t)i * DK;
        P *= us[i][d];
        float qv = q[idx];
        float kv = k[idx];
        g_QE[idx] = qv * (P * invs);
        g_KE[idx] = kv * (sq_ / P);
        g_qb[idx] = qv * P;
        g_kd[idx] = kv * (Pl / P);
    }
    g_el[cc * DK + d] = Pl;
}

// ---------------- A = tril(QE @ KE^T) per chunk (64x64, K=128) ----------------
__global__ __launch_bounds__(256) void a_gemm()
{
    int cc = blockIdx.x;
    int tid = threadIdx.x, tx = tid & 15, ty = tid >> 4;
    __shared__ float Qs[64][33];
    __shared__ float Ks[64][33];
    float acc[4][4] = {};
    const float* Q  = g_QE + (size_t)cc * CHUNK * DK;
    const float* Kp = g_KE + (size_t)cc * CHUNK * DK;
    for (int k0 = 0; k0 < DK; k0 += 32) {
#pragma unroll
        for (int rr = 0; rr < 8; rr++) {
            int idx = tid + 256 * rr;
            int row = idx >> 5, kk = idx & 31;
            Qs[row][kk] = Q [row * DK + k0 + kk];
            Ks[row][kk] = Kp[row * DK + k0 + kk];
        }
        __syncthreads();
#pragma unroll
        for (int kk = 0; kk < 32; kk++) {
            float a[4], b[4];
#pragma unroll
            for (int i = 0; i < 4; i++) a[i] = Qs[ty * 4 + i][kk];
#pragma unroll
            for (int j = 0; j < 4; j++) b[j] = Ks[tx * 4 + j][kk];
#pragma unroll
            for (int i = 0; i < 4; i++)
#pragma unroll
                for (int j = 0; j < 4; j++) acc[i][j] = fmaf(a[i], b[j], acc[i][j]);
        }
        __syncthreads();
    }
#pragma unroll
    for (int i = 0; i < 4; i++)
#pragma unroll
        for (int j = 0; j < 4; j++) {
            int I = ty * 4 + i, J = tx * 4 + j;
            g_A[(size_t)cc * CHUNK * CHUNK + I * CHUNK + J] = (J <= I) ? acc[i][j] : 0.f;
        }
}

// ---------------- T_c[d,v] = sum_i kd[i,d] * v[i,v]   (128x2048, K=64) --------
__global__ __launch_bounds__(256) void t_gemm(const float* __restrict__ x)
{
    int cc = blockIdx.y;
    int vb = blockIdx.x * 64;
    int tid = threadIdx.x, tx = tid & 15, ty = tid >> 4;
    __shared__ __align__(16) float kds[32][132];   // [i(k)][d]
    __shared__ __align__(16) float xs[32][68];     // [i(k)][v]
    float acc[8][4] = {};
    const float* kd = g_kd + (size_t)cc * CHUNK * DK;

    for (int k0 = 0; k0 < CHUNK; k0 += 32) {
#pragma unroll
        for (int rr = 0; rr < 4; rr++) {              // kd tile 32x128
            int idx = tid + 256 * rr;
            int row = idx >> 5, seg = idx & 31;
            *(float4*)&kds[row][seg * 4] =
                *(const float4*)(kd + (size_t)(k0 + row) * DK + seg * 4);
        }
#pragma unroll
        for (int rr = 0; rr < 2; rr++) {              // v tile 32x64
            int idx = tid + 256 * rr;
            int row = idx >> 4, seg = idx & 15;
            *(float4*)&xs[row][seg * 4] =
                *(const float4*)(x + (size_t)(cc * CHUNK + k0 + row) * HID + vb + seg * 4);
        }
        __syncthreads();
#pragma unroll
        for (int kk = 0; kk < 32; kk++) {
            float a[8], b[4];
            *(float4*)&a[0] = *(float4*)&kds[kk][ty * 8];
            *(float4*)&a[4] = *(float4*)&kds[kk][ty * 8 + 4];
            *(float4*)&b[0] = *(float4*)&xs[kk][tx * 4];
#pragma unroll
            for (int i = 0; i < 8; i++)
#pragma unroll
                for (int j = 0; j < 4; j++) acc[i][j] = fmaf(a[i], b[j], acc[i][j]);
        }
        __syncthreads();
    }
    float* T = g_T + (size_t)cc * DK * HID;
#pragma unroll
    for (int i = 0; i < 8; i++) {
        float4 o4 = make_float4(acc[i][0], acc[i][1], acc[i][2], acc[i][3]);
        *(float4*)(T + (size_t)(ty * 8 + i) * HID + vb + tx * 4) = o4;
    }
}

// ---------------- chunk-state scan: in-place T -> S_before --------------------
__global__ void scan_k()
{
    int gid = blockIdx.x * blockDim.x + threadIdx.x;   // 131072 threads
    int vg = gid & 511;
    int rest = gid >> 9;
    int d = rest & 127;
    int b = rest >> 7;
    float4 s = make_float4(0.f, 0.f, 0.f, 0.f);
    for (int c = 0; c < NCHUNK; c++) {
        int cc = b * NCHUNK + c;
        float e = g_el[cc * DK + d];
        float4* p = (float4*)&g_T[((size_t)cc * DK + d) * HID + vg * 4];
        float4 t = *p;
        *p = s;                                        // S before chunk c
        s.x = fmaf(s.x, e, t.x);
        s.y = fmaf(s.y, e, t.y);
        s.z = fmaf(s.z, e, t.z);
        s.w = fmaf(s.w, e, t.w);
    }
}

// ---------------- o = A @ v + qb @ S_before (64x2048 per chunk) ---------------
__global__ __launch_bounds__(256) void o_gemm(const float* __restrict__ x)
{
    int cc = blockIdx.y;
    int vb = blockIdx.x * 64;
    int tid = threadIdx.x, tx = tid & 15, ty = tid >> 4;
    __shared__ float Ls[64][33];
    __shared__ float Rs[32][65];
    float acc[4][4] = {};

    for (int ph = 0; ph < 2; ph++) {
        int KK = ph ? DK : CHUNK;
        const float* L = ph ? (g_qb + (size_t)cc * CHUNK * DK)
                            : (g_A + (size_t)cc * CHUNK * CHUNK);
        int lstride = ph ? DK : CHUNK;
        for (int k0 = 0; k0 < KK; k0 += 32) {
#pragma unroll
            for (int rr = 0; rr < 8; rr++) {          // LHS tile 64x32
                int idx = tid + 256 * rr;
                int row = idx >> 5, kk = idx & 31;
                Ls[row][kk] = L[(size_t)row * lstride + k0 + kk];
            }
#pragma unroll
            for (int rr = 0; rr < 8; rr++) {          // RHS tile 32x64
                int idx = tid + 256 * rr;
                int kk = idx >> 6, v = idx & 63;
                float val;
                if (ph == 0)
                    val = x[(size_t)(cc * CHUNK + k0 + kk) * HID + vb + v];
                else
                    val = g_T[(size_t)cc * DK * HID + (size_t)(k0 + kk) * HID + vb + v];
                Rs[kk][v] = val;
            }
            __syncthreads();
#pragma unroll
            for (int kk = 0; kk < 32; kk++) {
                float a[4], b[4];
#pragma unroll
                for (int i = 0; i < 4; i++) a[i] = Ls[ty * 4 + i][kk];
#pragma unroll
                for (int j = 0; j < 4; j++) b[j] = Rs[kk][tx * 4 + j];
#pragma unroll
                for (int i = 0; i < 4; i++)
#pragma unroll
                    for (int j = 0; j < 4; j++) acc[i][j] = fmaf(a[i], b[j], acc[i][j]);
            }
            __syncthreads();
        }
    }
#pragma unroll
    for (int i = 0; i < 4; i++) {
        size_t rowel = (size_t)(cc * CHUNK + ty * 4 + i) * HID + vb + tx * 4;
        *(float4*)&g_o[rowel] = make_float4(acc[i][0], acc[i][1], acc[i][2], acc[i][3]);
    }
}

// ---------------- t = rmsnorm(o)*gw * silu(G); quantize t in-kernel -----------
__global__ __launch_bounds__(256) void gate_norm(const float* __restrict__ o,
                                                 const float* __restrict__ G,
                                                 const float* __restrict__ gw,
                                                 int8_t* __restrict__ t0p,
                                                 int8_t* __restrict__ t1p,
                                                 float* __restrict__ stp)
{
    int t = blockIdx.x, tid = threadIdx.x;
    int lane = tid & 31, w = tid >> 5;
    const float2* o2 = (const float2*)(o + (size_t)t * HID);
    const float2* G2 = (const float2*)(G + (size_t)t * HID);
    const float2* w2 = (const float2*)gw;
    float s = 0.f;
    float2 ovs[4];
#pragma unroll
    for (int j = 0; j < 4; j++) {
        ovs[j] = o2[tid + j * 256];
        s = fmaf(ovs[j].x, ovs[j].x, s); s = fmaf(ovs[j].y, ovs[j].y, s);
    }
#pragma unroll
    for (int off = 16; off; off >>= 1) s += __shfl_xor_sync(0xffffffffu, s, off);
    __shared__ float red[8];
    if (!lane) red[w] = s;
    __syncthreads();
    float tot = 0.f;
#pragma unroll
    for (int i = 0; i < 8; i++) tot += red[i];
    float rr = rsqrtf(tot * (1.0f / HID) + 1e-5f);

    float tv[8];
    float am = 0.f;
#pragma unroll
    for (int j = 0; j < 4; j++) {
        int idx = tid + j * 256;
        float2 gv = G2[idx], wv = w2[idx];
        float t0 = ovs[j].x * rr * wv.x * (gv.x / (1.f + expf(-gv.x)));
        float t1 = ovs[j].y * rr * wv.y * (gv.y / (1.f + expf(-gv.y)));
        tv[2 * j] = t0; tv[2 * j + 1] = t1;
        am = fmaxf(am, fmaxf(fabsf(t0), fabsf(t1)));
    }
#pragma unroll
    for (int off = 16; off; off >>= 1) am = fmaxf(am, __shfl_xor_sync(0xffffffffu, am, off));
    __shared__ float red2[8];
    if (!lane) red2[w] = am;
    __syncthreads();
    float amax = red2[0];
#pragma unroll
    for (int i = 1; i < 8; i++) amax = fmaxf(amax, red2[i]);
    float sc = (amax > 0.f) ? amax : 1.f;
    if (tid == 0) stp[t] = sc * (1.f / 127.f);
    float inv = 127.f / sc;
#pragma unroll
    for (int j = 0; j < 4; j++) {
        int idx = tid + j * 256;
        int8_t a0, b0, a1, b1;
        enc2(tv[2 * j] * inv, a0, b0);
        enc2(tv[2 * j + 1] * inv, a1, b1);
        *(char2*)(t0p + (size_t)t * HID + 2 * idx) = make_char2(a0, a1);
        *(char2*)(t1p + (size_t)t * HID + 2 * idx) = make_char2(b0, b1);
    }
}

// ---------------- launch ------------------------------------------------------
extern "C" void kernel_launch(void* const* d_in, const int* in_sizes, int n_in,
                              void* d_out, int out_size)
{
    const float* x   = (const float*)d_in[0];
    const float* Wq  = (const float*)d_in[1];
    const float* Wk  = (const float*)d_in[2];
    const float* Wog = (const float*)d_in[3];
    const float* Wig = (const float*)d_in[4];
    const float* Wo  = (const float*)d_in[5];
    const float* gw  = (const float*)d_in[6];
    float* out = (float*)d_out;

    float *sq, *sk, *o_, *G;
    cudaGetSymbolAddress((void**)&sq, g_sq);
    cudaGetSymbolAddress((void**)&sk, g_sk);
    cudaGetSymbolAddress((void**)&o_, g_o);
    cudaGetSymbolAddress((void**)&G,  g_G);
    int8_t *x0, *x1, *wq0, *wq1, *wk0, *wk1, *wog0, *wog1, *wig0, *wig1, *wo0, *wo1;
    int8_t *o0, *o1, *t0, *t1;
    float *sx, *swq, *swk, *swog, *swig, *swo, *so, *st;
    cudaGetSymbolAddress((void**)&x0, g_x0);   cudaGetSymbolAddress((void**)&x1, g_x1);
    cudaGetSymbolAddress((void**)&sx, g_sx);
    cudaGetSymbolAddress((void**)&wq0, g_wq0); cudaGetSymbolAddress((void**)&wq1, g_wq1);
    cudaGetSymbolAddress((void**)&swq, g_swq);
    cudaGetSymbolAddress((void**)&wk0, g_wk0); cudaGetSymbolAddress((void**)&wk1, g_wk1);
    cudaGetSymbolAddress((void**)&swk, g_swk);
    cudaGetSymbolAddress((void**)&wog0, g_wog0); cudaGetSymbolAddress((void**)&wog1, g_wog1);
    cudaGetSymbolAddress((void**)&swog, g_swog);
    cudaGetSymbolAddress((void**)&wig0, g_wig0); cudaGetSymbolAddress((void**)&wig1, g_wig1);
    cudaGetSymbolAddress((void**)&swig, g_swig);
    cudaGetSymbolAddress((void**)&wo0, g_wo0); cudaGetSymbolAddress((void**)&wo1, g_wo1);
    cudaGetSymbolAddress((void**)&swo, g_swo);
    cudaGetSymbolAddress((void**)&o0, g_o0);   cudaGetSymbolAddress((void**)&o1, g_o1);
    cudaGetSymbolAddress((void**)&so, g_so);
    cudaGetSymbolAddress((void**)&t0, g_t0);   cudaGetSymbolAddress((void**)&t1, g_t1);
    cudaGetSymbolAddress((void**)&st, g_st);

    cudaFuncSetAttribute(im_gemm, cudaFuncAttributeMaxDynamicSharedMemorySize, GSMEM);

    const float WC = 1.f / 128.f;

    // 0. quantize x ; 1. quantize Wq+Wk (fused)
    quant_rows<<<dim3(NTOK, 1), 256>>>(x, x0, x1, sx, x, x0, x1, sx, x, x0, x1, sx);
    quant_rows<<<dim3(DK, 2), 256>>>(Wq, wq0, wq1, swq, Wk, wk0, wk1, swk, Wk, wk0, wk1, swk);

    // 2-3. q,k projections: cross (write) + main (accum); z fuses q/k
    im_gemm<<<dim3(1, NTOK / 128, 2), 256, GSMEM>>>(
        x0, x1, wq1, wq0, sq, sx, swq, wk1, wk0, sk, swk,
        WC, 0, 2, 1, HID, DK);
    im_gemm<<<dim3(1, NTOK / 128, 2), 256, GSMEM>>>(
        x0, x0, wq0, wq0, sq, sx, swq, wk0, wk0, sk, swk,
        1.f, 1, 1, 1, HID, DK);

    // 4. softmax / sigmoid ; 5. per-chunk decay factors
    qk_act<<<NTOK, DK>>>(sq, sk);
    chunk_prep<<<NCC, DK>>>(sq, sk);

    // 6. quantize Wog/Wig/Wo (fused triple)
    quant_rows<<<dim3(HID, 3), 256>>>(Wog, wog0, wog1, swog,
                                      Wig, wig0, wig1, swig,
                                      Wo,  wo0,  wo1,  swo);

    // 7-10. attention middle
    a_gemm<<<NCC, 256>>>();
    t_gemm<<<dim3(HID / 64, NCC), 256>>>(x);
    scan_k<<<512, 256>>>();
    o_gemm<<<dim3(HID / 64, NCC), 256>>>(x);

    // 11. quantize o
    quant_rows<<<dim3(NTOK, 1), 256>>>(o_, o0, o1, so, o_, o0, o1, so, o_, o0, o1, so);

    // 12-15. gates: G = o@Wog^T + x@Wig^T  (4 int8 segments)
    im_gemm<<<dim3(HID / 128, NTOK / 128, 1), 256, GSMEM>>>(
        o0, o1, wog1, wog0, G, so, swog, wog1, wog0, G, swog,
        WC, 0, 2, 0, HID, HID);
    im_gemm<<<dim3(HID / 128, NTOK / 128, 1), 256, GSMEM>>>(
        o0, o0, wog0, wog0, G, so, swog, wog0, wog0, G, swog,
        1.f, 1, 1, 0, HID, HID);
    im_gemm<<<dim3(HID / 128, NTOK / 128, 1), 256, GSMEM>>>(
        x0, x1, wig1, wig0, G, sx, swig, wig1, wig0, G, swig,
        WC, 1, 2, 0, HID, HID);
    im_gemm<<<dim3(HID / 128, NTOK / 128, 1), 256, GSMEM>>>(
        x0, x0, wig0, wig0, G, sx, swig, wig0, wig0, G, swig,
        1.f, 1, 1, 0, HID, HID);

    // 16. rmsnorm + silu gating -> quantized t
    gate_norm<<<NTOK, 256>>>(o_, G, gw, t0, t1, st);

    // 17-18. final projection: out = t @ Wo^T
    im_gemm<<<dim3(HID / 128, NTOK / 128, 1), 256, GSMEM>>>(
        t0, t1, wo1, wo0, out, st, swo, wo1, wo0, out, swo,
        WC, 0, 2, 0, HID, HID);
    im_gemm<<<dim3(HID / 128, NTOK / 128, 1), 256, GSMEM>>>(
        t0, t0, wo0, wo0, out, st, swo, wo0, wo0, out, swo,
        1.f, 1, 1, 0, HID, HID);
}

// round 11
// speedup vs baseline: 4.3632x; 4.3632x over previous
#include <cuda_runtime.h>
#include <cuda_fp16.h>
#include <cstdint>
#include <math.h>

// Problem constants
#define BATCH 2
#define SEQ   4096
#define HID   2048
#define DK    128
#define CHUNK 64
#define NCHUNK 64                  // per batch
#define NCC   (BATCH*NCHUNK)       // 128 total batch-chunks
#define NTOK  (BATCH*SEQ)          // 8192

// ---------------- fp32 scratch ------------------------------------------------
__device__ float g_sq[(size_t)NTOK*DK];         // q scores -> q (softmax)
__device__ float g_sk[(size_t)NTOK*DK];         // k scores -> k (sigmoid)
__device__ float g_QE[(size_t)NCC*CHUNK*DK];    // q * exp(B - Bm)
__device__ float g_KE[(size_t)NCC*CHUNK*DK];    // k * exp(Bm - B)
__device__ float g_qb[(size_t)NCC*CHUNK*DK];    // q * exp(B)
__device__ float g_kd[(size_t)NCC*CHUNK*DK];    // k * exp(Blast - B)
__device__ float g_el[NCC*DK];                  // exp(Blast)
__device__ float g_A [(size_t)NCC*CHUNK*CHUNK]; // tril intra matrices
__device__ float g_T [(size_t)NCC*DK*HID];      // T_c then (in-place) S_before_c
__device__ float g_o [(size_t)NTOK*HID];        // attention output o (fp32)
__device__ float g_G [(size_t)NTOK*HID];        // gate scores

// ---------------- fp16 operand scratch ------------------------------------------
// Weights get a two-level split (w = w0 + w1, exact to ~2^-22); activations are
// single fp16 (the sole GEMM error source, ~2e-4).
__device__ __align__(16) __half g_xh  [(size_t)NTOK*HID];
__device__ __align__(16) __half g_wq0 [(size_t)DK*HID];
__device__ __align__(16) __half g_wq1 [(size_t)DK*HID];
__device__ __align__(16) __half g_wk0 [(size_t)DK*HID];
__device__ __align__(16) __half g_wk1 [(size_t)DK*HID];
__device__ __align__(16) __half g_wog0[(size_t)HID*HID];
__device__ __align__(16) __half g_wog1[(size_t)HID*HID];
__device__ __align__(16) __half g_wig0[(size_t)HID*HID];
__device__ __align__(16) __half g_wig1[(size_t)HID*HID];
__device__ __align__(16) __half g_wo0 [(size_t)HID*HID];
__device__ __align__(16) __half g_wo1 [(size_t)HID*HID];
__device__ __align__(16) __half g_ohf [(size_t)NTOK*HID];
__device__ __align__(16) __half g_thf [(size_t)NTOK*HID];

// ---------------- helpers -----------------------------------------------------
__device__ __forceinline__ uint32_t smem_u32(const void* p) {
    uint32_t a;
    asm("{ .reg .u64 t; cvta.to.shared.u64 t, %1; cvt.u32.u64 %0, t; }" : "=r"(a) : "l"(p));
    return a;
}
#define CPASYNC16(dst, src) \
    asm volatile("cp.async.cg.shared.global [%0], [%1], 16;" :: "r"(dst), "l"(src) : "memory")
#define CPCOMMIT() asm volatile("cp.async.commit_group;" ::: "memory")
#define CPWAIT1()  asm volatile("cp.async.wait_group 1;" ::: "memory")
#define CPWAIT0()  asm volatile("cp.async.wait_group 0;" ::: "memory")
#define LDSM4(r0, r1, r2, r3, addr) \
    asm volatile("ldmatrix.sync.aligned.m8n8.x4.shared.b16 {%0,%1,%2,%3}, [%4];" \
        : "=r"(r0), "=r"(r1), "=r"(r2), "=r"(r3) : "r"(addr))

__device__ __forceinline__ void mma16h(float* c, const uint32_t* a, const uint32_t* b) {
    asm volatile(
        "mma.sync.aligned.m16n8k16.row.col.f32.f16.f16.f32 "
        "{%0,%1,%2,%3}, {%4,%5,%6,%7}, {%8,%9}, {%0,%1,%2,%3};"
        : "+f"(c[0]), "+f"(c[1]), "+f"(c[2]), "+f"(c[3])
        : "r"(a[0]), "r"(a[1]), "r"(a[2]), "r"(a[3]), "r"(b[0]), "r"(b[1]));
}

// ---------------- fp32 -> fp16 single conversion --------------------------------
__global__ void cvt_h1(const float4* __restrict__ src, __half2* __restrict__ dst, int n4)
{
    int i = blockIdx.x * blockDim.x + threadIdx.x;
    if (i >= n4) return;
    float4 v = src[i];
    dst[2 * i]     = __floats2half2_rn(v.x, v.y);
    dst[2 * i + 1] = __floats2half2_rn(v.z, v.w);
}

// ---------------- fp32 -> fp16 two-level split (up to 3 tensors per launch) ----
__global__ void cvt_h2(const float4* __restrict__ s0, __half2* h00, __half2* h01,
                       const float4* __restrict__ s1, __half2* h10, __half2* h11,
                       const float4* __restrict__ s2, __half2* h20, __half2* h21,
                       int n4)
{
    const float4* src; __half2 *d0, *d1;
    if (blockIdx.y == 0)      { src = s0; d0 = h00; d1 = h01; }
    else if (blockIdx.y == 1) { src = s1; d0 = h10; d1 = h11; }
    else                      { src = s2; d0 = h20; d1 = h21; }
    int i = blockIdx.x * blockDim.x + threadIdx.x;
    if (i >= n4) return;
    float4 v = src[i];
    __half a0 = __float2half_rn(v.x), a1 = __float2half_rn(v.y);
    __half a2 = __float2half_rn(v.z), a3 = __float2half_rn(v.w);
    d0[2 * i]     = __halves2half2(a0, a1);
    d0[2 * i + 1] = __halves2half2(a2, a3);
    d1[2 * i]     = __floats2half2_rn(v.x - __half2float(a0), v.y - __half2float(a1));
    d1[2 * i + 1] = __floats2half2_rn(v.z - __half2float(a2), v.w - __half2float(a3));
}

// ============ fp16 mma.sync GEMM: C[M,Ncols] = sum_ph A_ph[M,K]@B_ph[n,K]^T ====
// CTA 128x128, 8 warps (2x4), warp 64x32, K-chunk 64 fp16.
// 3-stage cp.async pipeline, single __syncthreads per chunk. Phase t>>5 selects
// the (A,B) operand pair (K=2048 -> 32 chunks per phase); up to 4 phases.
// zsplit: blockIdx.z==1 uses phases 2..3 and C1 (q/k fusion).
#define KC 64
#define PITCHB 144                 // bytes per smem row (64 fp16 + 16B pad)
#define TILEB (128 * PITCHB)       // 18432
#define STAGEB (2 * TILEB)         // 36864 (A tile + B tile)
#define NSTG 3
#define GSMEM (NSTG * STAGEB)      // 110592

__global__ void __launch_bounds__(256, 2) tm_gemm(
    const __half* __restrict__ A0, const __half* __restrict__ A1,
    const __half* __restrict__ A2, const __half* __restrict__ A3,
    const __half* __restrict__ B0, const __half* __restrict__ B1,
    const __half* __restrict__ B2, const __half* __restrict__ B3,
    float* __restrict__ C0, float* __restrict__ C1,
    int nphase, int zsplit, int K, int Ncols)
{
    extern __shared__ char smc[];
    const int tid = threadIdx.x, lane = tid & 31, wid = tid >> 5;
    const int wm = wid & 1, wn = wid >> 1;
    const int r = lane >> 2, kq = lane & 3;
    const long bm = (long)blockIdx.y * 128;
    const long bn = (long)blockIdx.x * 128;

    int pbeg = 0, pcnt = nphase;
    float* C = C0;
    if (zsplit) { pcnt = 2; if (blockIdx.z) { pbeg = 2; C = C1; } }
    const int nT = pcnt * 32;            // K == 2048 -> 32 chunks per phase

    float acc[4][4][4];
#pragma unroll
    for (int i = 0; i < 4; i++)
#pragma unroll
        for (int j = 0; j < 4; j++)
#pragma unroll
            for (int t = 0; t < 4; t++) acc[i][j][t] = 0.f;

    const uint32_t sb = smem_u32(smc);

    auto getAB = [&](int t, const __half*& a, const __half*& b, int& k0) {
        int ph = pbeg + (t >> 5);
        k0 = (t & 31) * KC;
        switch (ph) {
            case 0: a = A0; b = B0; break;
            case 1: a = A1; b = B1; break;
            case 2: a = A2; b = B2; break;
            default: a = A3; b = B3; break;
        }
    };

    auto issue = [&](int t, int stg) {
        const __half *Ap, *Bp; int k0;
        getAB(t, Ap, Bp, k0);
        uint32_t As = sb + stg * STAGEB;
        uint32_t Bs = As + TILEB;
#pragma unroll
        for (int i = 0; i < 4; i++) {
            int u = tid + i * 256;
            int row = u >> 3, s = u & 7;
            CPASYNC16(As + row * PITCHB + s * 16, Ap + (bm + row) * (long)K + k0 + s * 8);
            CPASYNC16(Bs + row * PITCHB + s * 16, Bp + (bn + row) * (long)K + k0 + s * 8);
        }
        CPCOMMIT();
    };

    // ldmatrix per-lane byte offsets within a tile
    const int lm = lane >> 3, li = lane & 7;
    uint32_t aoff[4], boff[2];
#pragma unroll
    for (int mt = 0; mt < 4; mt++) {
        int arow = wm * 64 + mt * 16 + (lm & 1) * 8 + li;
        aoff[mt] = (uint32_t)(arow * PITCHB + (lm >> 1) * 16);
    }
#pragma unroll
    for (int p = 0; p < 2; p++) {
        int nt = 2 * p + (lm >> 1);
        int brow = wn * 32 + nt * 8 + li;
        boff[p] = (uint32_t)(brow * PITCHB + (lm & 1) * 16);
    }

    issue(0, 0);
    issue(1, 1);

    int st = 0, ist = 2;                 // compute stage / prefetch stage
    for (int t = 0; t < nT; t++) {
        if (t == nT - 1) CPWAIT0(); else CPWAIT1();
        __syncthreads();                 // stage t visible; stage ist free
        if (t + 2 < nT) issue(t + 2, ist);
        uint32_t As = sb + st * STAGEB;
        uint32_t Bs = As + TILEB;
#pragma unroll
        for (int ks = 0; ks < 4; ks++) {
            uint32_t af[4][4], bfr[2][4];
#pragma unroll
            for (int mt = 0; mt < 4; mt++)
                LDSM4(af[mt][0], af[mt][1], af[mt][2], af[mt][3], As + aoff[mt] + ks * 32);
#pragma unroll
            for (int p = 0; p < 2; p++)
                LDSM4(bfr[p][0], bfr[p][1], bfr[p][2], bfr[p][3], Bs + boff[p] + ks * 32);
#pragma unroll
            for (int mt = 0; mt < 4; mt++) {
                mma16h(acc[mt][0], af[mt], &bfr[0][0]);
                mma16h(acc[mt][1], af[mt], &bfr[0][2]);
                mma16h(acc[mt][2], af[mt], &bfr[1][0]);
                mma16h(acc[mt][3], af[mt], &bfr[1][2]);
            }
        }
        st = (st == NSTG - 1) ? 0 : st + 1;
        ist = (ist == NSTG - 1) ? 0 : ist + 1;
    }

    // epilogue
#pragma unroll
    for (int mt = 0; mt < 4; mt++) {
        long row = bm + wm * 64 + mt * 16 + r;
#pragma unroll
        for (int nt = 0; nt < 4; nt++) {
            long col = bn + wn * 32 + nt * 8 + kq * 2;
            *(float2*)&C[row * (long)Ncols + col] =
                make_float2(acc[mt][nt][0], acc[mt][nt][1]);
            *(float2*)&C[(row + 8) * (long)Ncols + col] =
                make_float2(acc[mt][nt][2], acc[mt][nt][3]);
        }
    }
}

// ---------------- q softmax / k sigmoid (in-place on score buffers) -----------
__global__ void qk_act(float* __restrict__ sq, float* __restrict__ sk)
{
    int t = blockIdx.x, d = threadIdx.x;            // 128 threads
    int lane = d & 31, w = d >> 5;
    __shared__ float sm[4], ss[4];
    size_t idx = (size_t)t * DK + d;
    float v = sq[idx];
    float m = v;
#pragma unroll
    for (int o = 16; o; o >>= 1) m = fmaxf(m, __shfl_xor_sync(0xffffffffu, m, o));
    if (!lane) sm[w] = m;
    __syncthreads();
    m = fmaxf(fmaxf(sm[0], sm[1]), fmaxf(sm[2], sm[3]));
    float e = expf(v - m);
    float s = e;
#pragma unroll
    for (int o = 16; o; o >>= 1) s += __shfl_xor_sync(0xffffffffu, s, o);
    if (!lane) ss[w] = s;
    __syncthreads();
    s = ss[0] + ss[1] + ss[2] + ss[3];
    sq[idx] = e / s;
    float kv = sk[idx];
    sk[idx] = 1.f / (1.f + expf(-kv));
}

// ---------------- per-chunk decay prep (product form) -------------------------
// exp(gf) = sigmoid(-k); exp(B_i) = running product P of sigmoid(-k_j).
__global__ void chunk_prep(const float* __restrict__ q, const float* __restrict__ k)
{
    int cc = blockIdx.x;
    int d = threadIdx.x;                 // 128 threads
    __shared__ float us[CHUNK][DK];
    size_t base = (size_t)cc * CHUNK * DK + d;
    float P = 1.f;
#pragma unroll 4
    for (int i = 0; i < CHUNK; i++) {
        float kv = k[base + (size_t)i * DK];
        float u = 1.f / (1.f + expf(kv));
        us[i][d] = u;
        P *= u;
    }
    float Pl = P;
    float invs = rsqrtf(Pl);
    float sq_ = sqrtf(Pl);
    P = 1.f;
#pragma unroll 4
    for (int i = 0; i < CHUNK; i++) {
        size_t idx = base + (size_t)i * DK;
        P *= us[i][d];
        float qv = q[idx];
        float kv = k[idx];
        g_QE[idx] = qv * (P * invs);
        g_KE[idx] = kv * (sq_ / P);
        g_qb[idx] = qv * P;
        g_kd[idx] = kv * (Pl / P);
    }
    g_el[cc * DK + d] = Pl;
}

// ---------------- A = tril(QE @ KE^T) per chunk (64x64, K=128) ----------------
__global__ __launch_bounds__(256) void a_gemm()
{
    int cc = blockIdx.x;
    int tid = threadIdx.x, tx = tid & 15, ty = tid >> 4;
    __shared__ float Qs[64][33];
    __shared__ float Ks[64][33];
    float acc[4][4] = {};
    const float* Q  = g_QE + (size_t)cc * CHUNK * DK;
    const float* Kp = g_KE + (size_t)cc * CHUNK * DK;
    for (int k0 = 0; k0 < DK; k0 += 32) {
#pragma unroll
        for (int rr = 0; rr < 8; rr++) {
            int idx = tid + 256 * rr;
            int row = idx >> 5, kk = idx & 31;
            Qs[row][kk] = Q [row * DK + k0 + kk];
            Ks[row][kk] = Kp[row * DK + k0 + kk];
        }
        __syncthreads();
#pragma unroll
        for (int kk = 0; kk < 32; kk++) {
            float a[4], b[4];
#pragma unroll
            for (int i = 0; i < 4; i++) a[i] = Qs[ty * 4 + i][kk];
#pragma unroll
            for (int j = 0; j < 4; j++) b[j] = Ks[tx * 4 + j][kk];
#pragma unroll
            for (int i = 0; i < 4; i++)
#pragma unroll
                for (int j = 0; j < 4; j++) acc[i][j] = fmaf(a[i], b[j], acc[i][j]);
        }
        __syncthreads();
    }
#pragma unroll
    for (int i = 0; i < 4; i++)
#pragma unroll
        for (int j = 0; j < 4; j++) {
            int I = ty * 4 + i, J = tx * 4 + j;
            g_A[(size_t)cc * CHUNK * CHUNK + I * CHUNK + J] = (J <= I) ? acc[i][j] : 0.f;
        }
}

// ---------------- T_c[d,v] = sum_i kd[i,d] * v[i,v]   (128x2048, K=64) --------
__global__ __launch_bounds__(256) void t_gemm(const float* __restrict__ x)
{
    int cc = blockIdx.y;
    int vb = blockIdx.x * 64;
    int tid = threadIdx.x, tx = tid & 15, ty = tid >> 4;
    __shared__ __align__(16) float kds[32][132];   // [i(k)][d]
    __shared__ __align__(16) float xs[32][68];     // [i(k)][v]
    float acc[8][4] = {};
    const float* kd = g_kd + (size_t)cc * CHUNK * DK;

    for (int k0 = 0; k0 < CHUNK; k0 += 32) {
#pragma unroll
        for (int rr = 0; rr < 4; rr++) {              // kd tile 32x128
            int idx = tid + 256 * rr;
            int row = idx >> 5, seg = idx & 31;
            *(float4*)&kds[row][seg * 4] =
                *(const float4*)(kd + (size_t)(k0 + row) * DK + seg * 4);
        }
#pragma unroll
        for (int rr = 0; rr < 2; rr++) {              // v tile 32x64
            int idx = tid + 256 * rr;
            int row = idx >> 4, seg = idx & 15;
            *(float4*)&xs[row][seg * 4] =
                *(const float4*)(x + (size_t)(cc * CHUNK + k0 + row) * HID + vb + seg * 4);
        }
        __syncthreads();
#pragma unroll
        for (int kk = 0; kk < 32; kk++) {
            float a[8], b[4];
            *(float4*)&a[0] = *(float4*)&kds[kk][ty * 8];
            *(float4*)&a[4] = *(float4*)&kds[kk][ty * 8 + 4];
            *(float4*)&b[0] = *(float4*)&xs[kk][tx * 4];
#pragma unroll
            for (int i = 0; i < 8; i++)
#pragma unroll
                for (int j = 0; j < 4; j++) acc[i][j] = fmaf(a[i], b[j], acc[i][j]);
        }
        __syncthreads();
    }
    float* T = g_T + (size_t)cc * DK * HID;
#pragma unroll
    for (int i = 0; i < 8; i++) {
        float4 o4 = make_float4(acc[i][0], acc[i][1], acc[i][2], acc[i][3]);
        *(float4*)(T + (size_t)(ty * 8 + i) * HID + vb + tx * 4) = o4;
    }
}

// ---------------- chunk-state scan: in-place T -> S_before --------------------
__global__ void scan_k()
{
    int gid = blockIdx.x * blockDim.x + threadIdx.x;   // 131072 threads
    int vg = gid & 511;
    int rest = gid >> 9;
    int d = rest & 127;
    int b = rest >> 7;
    float4 s = make_float4(0.f, 0.f, 0.f, 0.f);
    for (int c = 0; c < NCHUNK; c++) {
        int cc = b * NCHUNK + c;
        float e = g_el[cc * DK + d];
        float4* p = (float4*)&g_T[((size_t)cc * DK + d) * HID + vg * 4];
        float4 t = *p;
        *p = s;                                        // S before chunk c
        s.x = fmaf(s.x, e, t.x);
        s.y = fmaf(s.y, e, t.y);
        s.z = fmaf(s.z, e, t.z);
        s.w = fmaf(s.w, e, t.w);
    }
}

// ---------------- o = A @ v + qb @ S_before (64x2048 per chunk) ---------------
// Writes o fp32 + single fp16 (A operand of the gate GEMM).
__global__ __launch_bounds__(256) void o_gemm(const float* __restrict__ x)
{
    int cc = blockIdx.y;
    int vb = blockIdx.x * 64;
    int tid = threadIdx.x, tx = tid & 15, ty = tid >> 4;
    __shared__ float Ls[64][33];
    __shared__ float Rs[32][65];
    float acc[4][4] = {};

    for (int ph = 0; ph < 2; ph++) {
        int KK = ph ? DK : CHUNK;
        const float* L = ph ? (g_qb + (size_t)cc * CHUNK * DK)
                            : (g_A + (size_t)cc * CHUNK * CHUNK);
        int lstride = ph ? DK : CHUNK;
        for (int k0 = 0; k0 < KK; k0 += 32) {
#pragma unroll
            for (int rr = 0; rr < 8; rr++) {          // LHS tile 64x32
                int idx = tid + 256 * rr;
                int row = idx >> 5, kk = idx & 31;
                Ls[row][kk] = L[(size_t)row * lstride + k0 + kk];
            }
#pragma unroll
            for (int rr = 0; rr < 8; rr++) {          // RHS tile 32x64
                int idx = tid + 256 * rr;
                int kk = idx >> 6, v = idx & 63;
                float val;
                if (ph == 0)
                    val = x[(size_t)(cc * CHUNK + k0 + kk) * HID + vb + v];
                else
                    val = g_T[(size_t)cc * DK * HID + (size_t)(k0 + kk) * HID + vb + v];
                Rs[kk][v] = val;
            }
            __syncthreads();
#pragma unroll
            for (int kk = 0; kk < 32; kk++) {
                float a[4], b[4];
#pragma unroll
                for (int i = 0; i < 4; i++) a[i] = Ls[ty * 4 + i][kk];
#pragma unroll
                for (int j = 0; j < 4; j++) b[j] = Rs[kk][tx * 4 + j];
#pragma unroll
                for (int i = 0; i < 4; i++)
#pragma unroll
                    for (int j = 0; j < 4; j++) acc[i][j] = fmaf(a[i], b[j], acc[i][j]);
            }
            __syncthreads();
        }
    }
#pragma unroll
    for (int i = 0; i < 4; i++) {
        size_t rowel = (size_t)(cc * CHUNK + ty * 4 + i) * HID + vb + tx * 4;
        float4 v = make_float4(acc[i][0], acc[i][1], acc[i][2], acc[i][3]);
        *(float4*)&g_o[rowel] = v;
        *(__half2*)&g_ohf[rowel]     = __floats2half2_rn(v.x, v.y);
        *(__half2*)&g_ohf[rowel + 2] = __floats2half2_rn(v.z, v.w);
    }
}

// ---------------- t = rmsnorm(o)*gw * silu(G) -> fp16 -------------------------
__global__ __launch_bounds__(256) void gate_norm(const float* __restrict__ o,
                                                 const float* __restrict__ G,
                                                 const float* __restrict__ gw,
                                                 __half* __restrict__ th)
{
    int t = blockIdx.x, tid = threadIdx.x;
    int lane = tid & 31, w = tid >> 5;
    const float2* o2 = (const float2*)(o + (size_t)t * HID);
    const float2* G2 = (const float2*)(G + (size_t)t * HID);
    const float2* w2 = (const float2*)gw;
    float s = 0.f;
    float2 ovs[4];
#pragma unroll
    for (int j = 0; j < 4; j++) {
        ovs[j] = o2[tid + j * 256];
        s = fmaf(ovs[j].x, ovs[j].x, s); s = fmaf(ovs[j].y, ovs[j].y, s);
    }
#pragma unroll
    for (int off = 16; off; off >>= 1) s += __shfl_xor_sync(0xffffffffu, s, off);
    __shared__ float red[8];
    if (!lane) red[w] = s;
    __syncthreads();
    float tot = 0.f;
#pragma unroll
    for (int i = 0; i < 8; i++) tot += red[i];
    float rr = rsqrtf(tot * (1.0f / HID) + 1e-5f);
    __half2* th2 = (__half2*)(th + (size_t)t * HID);
#pragma unroll
    for (int j = 0; j < 4; j++) {
        int idx = tid + j * 256;
        float2 gv = G2[idx], wv = w2[idx];
        float t0 = ovs[j].x * rr * wv.x * (gv.x / (1.f + expf(-gv.x)));
        float t1 = ovs[j].y * rr * wv.y * (gv.y / (1.f + expf(-gv.y)));
        th2[idx] = __floats2half2_rn(t0, t1);
    }
}

// ---------------- launch ------------------------------------------------------
extern "C" void kernel_launch(void* const* d_in, const int* in_sizes, int n_in,
                              void* d_out, int out_size)
{
    const float* x   = (const float*)d_in[0];
    const float* Wq  = (const float*)d_in[1];
    const float* Wk  = (const float*)d_in[2];
    const float* Wog = (const float*)d_in[3];
    const float* Wig = (const float*)d_in[4];
    const float* Wo  = (const float*)d_in[5];
    const float* gw  = (const float*)d_in[6];
    float* out = (float*)d_out;

    float *sq, *sk, *o_, *G;
    cudaGetSymbolAddress((void**)&sq, g_sq);
    cudaGetSymbolAddress((void**)&sk, g_sk);
    cudaGetSymbolAddress((void**)&o_, g_o);
    cudaGetSymbolAddress((void**)&G,  g_G);
    __half *xh, *wq0, *wq1, *wk0, *wk1, *wog0, *wog1, *wig0, *wig1, *wo0, *wo1;
    __half *ohf, *thf;
    cudaGetSymbolAddress((void**)&xh, g_xh);
    cudaGetSymbolAddress((void**)&wq0, g_wq0); cudaGetSymbolAddress((void**)&wq1, g_wq1);
    cudaGetSymbolAddress((void**)&wk0, g_wk0); cudaGetSymbolAddress((void**)&wk1, g_wk1);
    cudaGetSymbolAddress((void**)&wog0, g_wog0); cudaGetSymbolAddress((void**)&wog1, g_wog1);
    cudaGetSymbolAddress((void**)&wig0, g_wig0); cudaGetSymbolAddress((void**)&wig1, g_wig1);
    cudaGetSymbolAddress((void**)&wo0, g_wo0); cudaGetSymbolAddress((void**)&wo1, g_wo1);
    cudaGetSymbolAddress((void**)&ohf, g_ohf);
    cudaGetSymbolAddress((void**)&thf, g_thf);

    cudaFuncSetAttribute(tm_gemm, cudaFuncAttributeMaxDynamicSharedMemorySize, GSMEM);

    const int XN4 = NTOK * HID / 4, WN4 = HID * HID / 4, PN4 = DK * HID / 4;

    // 0. x -> fp16 single
    cvt_h1<<<XN4 / 256, 256>>>((const float4*)x, (__half2*)xh, XN4);
    // 1. Wq, Wk -> fp16 two-level
    cvt_h2<<<dim3(PN4 / 256, 2), 256>>>(
        (const float4*)Wq, (__half2*)wq0, (__half2*)wq1,
        (const float4*)Wk, (__half2*)wk0, (__half2*)wk1,
        (const float4*)Wk, (__half2*)wk0, (__half2*)wk1, PN4);
    // 2. Wog, Wig, Wo -> fp16 two-level
    cvt_h2<<<dim3(WN4 / 256, 3), 256>>>(
        (const float4*)Wog, (__half2*)wog0, (__half2*)wog1,
        (const float4*)Wig, (__half2*)wig0, (__half2*)wig1,
        (const float4*)Wo,  (__half2*)wo0,  (__half2*)wo1, WN4);

    // 3. q,k projections fused (z selects {Wq0,Wq1}->sq vs {Wk0,Wk1}->sk)
    tm_gemm<<<dim3(1, NTOK / 128, 2), 256, GSMEM>>>(
        xh, xh, xh, xh,
        wq0, wq1, wk0, wk1,
        sq, sk, 2, 1, HID, DK);
    // 4. softmax / sigmoid
    qk_act<<<NTOK, DK>>>(sq, sk);
    // 5. per-chunk decay factors
    chunk_prep<<<NCC, DK>>>(sq, sk);
    // 6. intra-chunk matrices
    a_gemm<<<NCC, 256>>>();
    // 7. per-chunk state contributions T_c
    t_gemm<<<dim3(HID / 64, NCC), 256>>>(x);
    // 8. recurrent scan (in-place: T -> S_before)
    scan_k<<<512, 256>>>();
    // 9. o = A@v + qb@S_before (+ fp16 epilogue)
    o_gemm<<<dim3(HID / 64, NCC), 256>>>(x);
    // 10. gates: G = o@Wog^T + x@Wig^T as 4 fp16 phases (one launch)
    tm_gemm<<<dim3(HID / 128, NTOK / 128, 1), 256, GSMEM>>>(
        ohf, ohf, xh, xh,
        wog0, wog1, wig0, wig1,
        G, G, 4, 0, HID, HID);
    // 11. rmsnorm + silu gating -> t fp16
    gate_norm<<<NTOK, 256>>>(o_, G, gw, thf);
    // 12. final projection: out = t @ Wo^T, 2 fp16 phases
    tm_gemm<<<dim3(HID / 128, NTOK / 128, 1), 256, GSMEM>>>(
        thf, thf, thf, thf,
        wo0, wo1, wo0, wo1,
        out, out, 2, 0, HID, HID);
}

// round 12
// speedup vs baseline: 5.9997x; 1.3751x over previous
#include <cuda_runtime.h>
#include <cuda_fp16.h>
#include <cstdint>
#include <math.h>

// Problem constants
#define BATCH 2
#define SEQ   4096
#define HID   2048
#define DK    128
#define CHUNK 64
#define NCHUNK 64                  // per batch
#define NCC   (BATCH*NCHUNK)       // 128 total batch-chunks
#define NTOK  (BATCH*SEQ)          // 8192

// ---------------- fp32 scratch ------------------------------------------------
__device__ float g_sq[(size_t)NTOK*DK];         // q scores -> q (softmax)
__device__ float g_sk[(size_t)NTOK*DK];         // k scores -> k (sigmoid)
__device__ float g_QE[(size_t)NCC*CHUNK*DK];    // q * exp(B - Bm)
__device__ float g_KE[(size_t)NCC*CHUNK*DK];    // k * exp(Bm - B)
__device__ float g_qb[(size_t)NCC*CHUNK*DK];    // q * exp(B)
__device__ float g_kd[(size_t)NCC*CHUNK*DK];    // k * exp(Blast - B)
__device__ float g_el[NCC*DK];                  // exp(Blast)
__device__ float g_A [(size_t)NCC*CHUNK*CHUNK]; // tril intra matrices
__device__ float g_T [(size_t)NCC*DK*HID];      // T_c then (in-place) S_before_c
__device__ float g_o [(size_t)NTOK*HID];        // attention output o (fp32)
__device__ float g_G [(size_t)NTOK*HID];        // gate scores

// ---------------- fp16 operand scratch ------------------------------------------
// q/k weights keep a two-level split (k feeds a 64-deep cumsum/exp chain);
// gate/final weights are single fp16 (error budget verified by measurement).
__device__ __align__(16) __half g_xh  [(size_t)NTOK*HID];
__device__ __align__(16) __half g_wq0 [(size_t)DK*HID];
__device__ __align__(16) __half g_wq1 [(size_t)DK*HID];
__device__ __align__(16) __half g_wk0 [(size_t)DK*HID];
__device__ __align__(16) __half g_wk1 [(size_t)DK*HID];
__device__ __align__(16) __half g_wogh[(size_t)HID*HID];
__device__ __align__(16) __half g_wigh[(size_t)HID*HID];
__device__ __align__(16) __half g_woh [(size_t)HID*HID];
__device__ __align__(16) __half g_ohf [(size_t)NTOK*HID];
__device__ __align__(16) __half g_thf [(size_t)NTOK*HID];

// ---------------- helpers -----------------------------------------------------
__device__ __forceinline__ uint32_t smem_u32(const void* p) {
    uint32_t a;
    asm("{ .reg .u64 t; cvta.to.shared.u64 t, %1; cvt.u32.u64 %0, t; }" : "=r"(a) : "l"(p));
    return a;
}
#define CPASYNC16(dst, src) \
    asm volatile("cp.async.cg.shared.global [%0], [%1], 16;" :: "r"(dst), "l"(src) : "memory")
#define CPCOMMIT() asm volatile("cp.async.commit_group;" ::: "memory")
#define CPWAIT1()  asm volatile("cp.async.wait_group 1;" ::: "memory")
#define CPWAIT0()  asm volatile("cp.async.wait_group 0;" ::: "memory")
#define LDSM4(r0, r1, r2, r3, addr) \
    asm volatile("ldmatrix.sync.aligned.m8n8.x4.shared.b16 {%0,%1,%2,%3}, [%4];" \
        : "=r"(r0), "=r"(r1), "=r"(r2), "=r"(r3) : "r"(addr))

__device__ __forceinline__ void mma16h(float* c, const uint32_t* a, const uint32_t* b) {
    asm volatile(
        "mma.sync.aligned.m16n8k16.row.col.f32.f16.f16.f32 "
        "{%0,%1,%2,%3}, {%4,%5,%6,%7}, {%8,%9}, {%0,%1,%2,%3};"
        : "+f"(c[0]), "+f"(c[1]), "+f"(c[2]), "+f"(c[3])
        : "r"(a[0]), "r"(a[1]), "r"(a[2]), "r"(a[3]), "r"(b[0]), "r"(b[1]));
}

// ---------------- fp32 -> fp16 single conversion (up to 3 tensors) -------------
__global__ void cvt_h1(const float4* __restrict__ s0, __half2* d0o,
                       const float4* __restrict__ s1, __half2* d1o,
                       const float4* __restrict__ s2, __half2* d2o, int n4)
{
    const float4* src; __half2* dst;
    if (blockIdx.y == 0)      { src = s0; dst = d0o; }
    else if (blockIdx.y == 1) { src = s1; dst = d1o; }
    else                      { src = s2; dst = d2o; }
    int i = blockIdx.x * blockDim.x + threadIdx.x;
    if (i >= n4) return;
    float4 v = src[i];
    dst[2 * i]     = __floats2half2_rn(v.x, v.y);
    dst[2 * i + 1] = __floats2half2_rn(v.z, v.w);
}

// ---------------- fp32 -> fp16 two-level split (up to 2 tensors) ---------------
__global__ void cvt_h2(const float4* __restrict__ s0, __half2* h00, __half2* h01,
                       const float4* __restrict__ s1, __half2* h10, __half2* h11,
                       int n4)
{
    const float4* src; __half2 *d0, *d1;
    if (blockIdx.y == 0) { src = s0; d0 = h00; d1 = h01; }
    else                 { src = s1; d0 = h10; d1 = h11; }
    int i = blockIdx.x * blockDim.x + threadIdx.x;
    if (i >= n4) return;
    float4 v = src[i];
    __half a0 = __float2half_rn(v.x), a1 = __float2half_rn(v.y);
    __half a2 = __float2half_rn(v.z), a3 = __float2half_rn(v.w);
    d0[2 * i]     = __halves2half2(a0, a1);
    d0[2 * i + 1] = __halves2half2(a2, a3);
    d1[2 * i]     = __floats2half2_rn(v.x - __half2float(a0), v.y - __half2float(a1));
    d1[2 * i + 1] = __floats2half2_rn(v.z - __half2float(a2), v.w - __half2float(a3));
}

// ============ fp16 mma.sync GEMM: C[M,Ncols] = sum_ph A_ph[M,K]@B_ph[n,K]^T ====
// CTA 128x128, 8 warps (2x4), warp 64x32, K-chunk 64 fp16.
// 3-stage cp.async pipeline, single __syncthreads per chunk. Phase t>>5 selects
// the (A,B) operand pair (K=2048 -> 32 chunks per phase); up to 4 phases.
// zsplit: blockIdx.z==1 uses phases 2..3 and C1 (q/k fusion).
#define KC 64
#define PITCHB 144                 // bytes per smem row (64 fp16 + 16B pad)
#define TILEB (128 * PITCHB)       // 18432
#define STAGEB (2 * TILEB)         // 36864 (A tile + B tile)
#define NSTG 3
#define GSMEM (NSTG * STAGEB)      // 110592

__global__ void __launch_bounds__(256, 2) tm_gemm(
    const __half* __restrict__ A0, const __half* __restrict__ A1,
    const __half* __restrict__ A2, const __half* __restrict__ A3,
    const __half* __restrict__ B0, const __half* __restrict__ B1,
    const __half* __restrict__ B2, const __half* __restrict__ B3,
    float* __restrict__ C0, float* __restrict__ C1,
    int nphase, int zsplit, int K, int Ncols)
{
    extern __shared__ char smc[];
    const int tid = threadIdx.x, lane = tid & 31, wid = tid >> 5;
    const int wm = wid & 1, wn = wid >> 1;
    const int r = lane >> 2, kq = lane & 3;
    const long bm = (long)blockIdx.y * 128;
    const long bn = (long)blockIdx.x * 128;

    int pbeg = 0, pcnt = nphase;
    float* C = C0;
    if (zsplit) { pcnt = 2; if (blockIdx.z) { pbeg = 2; C = C1; } }
    const int nT = pcnt * 32;            // K == 2048 -> 32 chunks per phase

    float acc[4][4][4];
#pragma unroll
    for (int i = 0; i < 4; i++)
#pragma unroll
        for (int j = 0; j < 4; j++)
#pragma unroll
            for (int t = 0; t < 4; t++) acc[i][j][t] = 0.f;

    const uint32_t sb = smem_u32(smc);

    auto getAB = [&](int t, const __half*& a, const __half*& b, int& k0) {
        int ph = pbeg + (t >> 5);
        k0 = (t & 31) * KC;
        switch (ph) {
            case 0: a = A0; b = B0; break;
            case 1: a = A1; b = B1; break;
            case 2: a = A2; b = B2; break;
            default: a = A3; b = B3; break;
        }
    };

    auto issue = [&](int t, int stg) {
        const __half *Ap, *Bp; int k0;
        getAB(t, Ap, Bp, k0);
        uint32_t As = sb + stg * STAGEB;
        uint32_t Bs = As + TILEB;
#pragma unroll
        for (int i = 0; i < 4; i++) {
            int u = tid + i * 256;
            int row = u >> 3, s = u & 7;
            CPASYNC16(As + row * PITCHB + s * 16, Ap + (bm + row) * (long)K + k0 + s * 8);
            CPASYNC16(Bs + row * PITCHB + s * 16, Bp + (bn + row) * (long)K + k0 + s * 8);
        }
        CPCOMMIT();
    };

    // ldmatrix per-lane byte offsets within a tile
    const int lm = lane >> 3, li = lane & 7;
    uint32_t aoff[4], boff[2];
#pragma unroll
    for (int mt = 0; mt < 4; mt++) {
        int arow = wm * 64 + mt * 16 + (lm & 1) * 8 + li;
        aoff[mt] = (uint32_t)(arow * PITCHB + (lm >> 1) * 16);
    }
#pragma unroll
    for (int p = 0; p < 2; p++) {
        int nt = 2 * p + (lm >> 1);
        int brow = wn * 32 + nt * 8 + li;
        boff[p] = (uint32_t)(brow * PITCHB + (lm & 1) * 16);
    }

    issue(0, 0);
    if (nT > 1) issue(1, 1);

    int st = 0, ist = 2;                 // compute stage / prefetch stage
    for (int t = 0; t < nT; t++) {
        if (t == nT - 1) CPWAIT0(); else CPWAIT1();
        __syncthreads();                 // stage t visible; stage ist free
        if (t + 2 < nT) issue(t + 2, ist);
        uint32_t As = sb + st * STAGEB;
        uint32_t Bs = As + TILEB;
#pragma unroll
        for (int ks = 0; ks < 4; ks++) {
            uint32_t af[4][4], bfr[2][4];
#pragma unroll
            for (int mt = 0; mt < 4; mt++)
                LDSM4(af[mt][0], af[mt][1], af[mt][2], af[mt][3], As + aoff[mt] + ks * 32);
#pragma unroll
            for (int p = 0; p < 2; p++)
                LDSM4(bfr[p][0], bfr[p][1], bfr[p][2], bfr[p][3], Bs + boff[p] + ks * 32);
#pragma unroll
            for (int mt = 0; mt < 4; mt++) {
                mma16h(acc[mt][0], af[mt], &bfr[0][0]);
                mma16h(acc[mt][1], af[mt], &bfr[0][2]);
                mma16h(acc[mt][2], af[mt], &bfr[1][0]);
                mma16h(acc[mt][3], af[mt], &bfr[1][2]);
            }
        }
        st = (st == NSTG - 1) ? 0 : st + 1;
        ist = (ist == NSTG - 1) ? 0 : ist + 1;
    }

    // epilogue
#pragma unroll
    for (int mt = 0; mt < 4; mt++) {
        long row = bm + wm * 64 + mt * 16 + r;
#pragma unroll
        for (int nt = 0; nt < 4; nt++) {
            long col = bn + wn * 32 + nt * 8 + kq * 2;
            *(float2*)&C[row * (long)Ncols + col] =
                make_float2(acc[mt][nt][0], acc[mt][nt][1]);
            *(float2*)&C[(row + 8) * (long)Ncols + col] =
                make_float2(acc[mt][nt][2], acc[mt][nt][3]);
        }
    }
}

// ---------------- q softmax / k sigmoid (in-place on score buffers) -----------
__global__ void qk_act(float* __restrict__ sq, float* __restrict__ sk)
{
    int t = blockIdx.x, d = threadIdx.x;            // 128 threads
    int lane = d & 31, w = d >> 5;
    __shared__ float sm[4], ss[4];
    size_t idx = (size_t)t * DK + d;
    float v = sq[idx];
    float m = v;
#pragma unroll
    for (int o = 16; o; o >>= 1) m = fmaxf(m, __shfl_xor_sync(0xffffffffu, m, o));
    if (!lane) sm[w] = m;
    __syncthreads();
    m = fmaxf(fmaxf(sm[0], sm[1]), fmaxf(sm[2], sm[3]));
    float e = expf(v - m);
    float s = e;
#pragma unroll
    for (int o = 16; o; o >>= 1) s += __shfl_xor_sync(0xffffffffu, s, o);
    if (!lane) ss[w] = s;
    __syncthreads();
    s = ss[0] + ss[1] + ss[2] + ss[3];
    sq[idx] = e / s;
    float kv = sk[idx];
    sk[idx] = 1.f / (1.f + expf(-kv));
}

// ---------------- per-chunk decay prep (product form) -------------------------
// exp(gf) = sigmoid(-k); exp(B_i) = running product P of sigmoid(-k_j).
__global__ void chunk_prep(const float* __restrict__ q, const float* __restrict__ k)
{
    int cc = blockIdx.x;
    int d = threadIdx.x;                 // 128 threads
    __shared__ float us[CHUNK][DK];
    size_t base = (size_t)cc * CHUNK * DK + d;
    float P = 1.f;
#pragma unroll 4
    for (int i = 0; i < CHUNK; i++) {
        float kv = k[base + (size_t)i * DK];
        float u = 1.f / (1.f + expf(kv));
        us[i][d] = u;
        P *= u;
    }
    float Pl = P;
    float invs = rsqrtf(Pl);
    float sq_ = sqrtf(Pl);
    P = 1.f;
#pragma unroll 4
    for (int i = 0; i < CHUNK; i++) {
        size_t idx = base + (size_t)i * DK;
        P *= us[i][d];
        float qv = q[idx];
        float kv = k[idx];
        g_QE[idx] = qv * (P * invs);
        g_KE[idx] = kv * (sq_ / P);
        g_qb[idx] = qv * P;
        g_kd[idx] = kv * (Pl / P);
    }
    g_el[cc * DK + d] = Pl;
}

// ---------------- A = tril(QE @ KE^T) per chunk (64x64, K=128) ----------------
__global__ __launch_bounds__(256) void a_gemm()
{
    int cc = blockIdx.x;
    int tid = threadIdx.x, tx = tid & 15, ty = tid >> 4;
    __shared__ float Qs[64][33];
    __shared__ float Ks[64][33];
    float acc[4][4] = {};
    const float* Q  = g_QE + (size_t)cc * CHUNK * DK;
    const float* Kp = g_KE + (size_t)cc * CHUNK * DK;
    for (int k0 = 0; k0 < DK; k0 += 32) {
#pragma unroll
        for (int rr = 0; rr < 8; rr++) {
            int idx = tid + 256 * rr;
            int row = idx >> 5, kk = idx & 31;
            Qs[row][kk] = Q [row * DK + k0 + kk];
            Ks[row][kk] = Kp[row * DK + k0 + kk];
        }
        __syncthreads();
#pragma unroll
        for (int kk = 0; kk < 32; kk++) {
            float a[4], b[4];
#pragma unroll
            for (int i = 0; i < 4; i++) a[i] = Qs[ty * 4 + i][kk];
#pragma unroll
            for (int j = 0; j < 4; j++) b[j] = Ks[tx * 4 + j][kk];
#pragma unroll
            for (int i = 0; i < 4; i++)
#pragma unroll
                for (int j = 0; j < 4; j++) acc[i][j] = fmaf(a[i], b[j], acc[i][j]);
        }
        __syncthreads();
    }
#pragma unroll
    for (int i = 0; i < 4; i++)
#pragma unroll
        for (int j = 0; j < 4; j++) {
            int I = ty * 4 + i, J = tx * 4 + j;
            g_A[(size_t)cc * CHUNK * CHUNK + I * CHUNK + J] = (J <= I) ? acc[i][j] : 0.f;
        }
}

// ---------------- T_c[d,v] = sum_i kd[i,d] * v[i,v]   (128x2048, K=64) --------
__global__ __launch_bounds__(256) void t_gemm(const float* __restrict__ x)
{
    int cc = blockIdx.y;
    int vb = blockIdx.x * 64;
    int tid = threadIdx.x, tx = tid & 15, ty = tid >> 4;
    __shared__ __align__(16) float kds[32][132];   // [i(k)][d]
    __shared__ __align__(16) float xs[32][68];     // [i(k)][v]
    float acc[8][4] = {};
    const float* kd = g_kd + (size_t)cc * CHUNK * DK;

    for (int k0 = 0; k0 < CHUNK; k0 += 32) {
#pragma unroll
        for (int rr = 0; rr < 4; rr++) {              // kd tile 32x128
            int idx = tid + 256 * rr;
            int row = idx >> 5, seg = idx & 31;
            *(float4*)&kds[row][seg * 4] =
                *(const float4*)(kd + (size_t)(k0 + row) * DK + seg * 4);
        }
#pragma unroll
        for (int rr = 0; rr < 2; rr++) {              // v tile 32x64
            int idx = tid + 256 * rr;
            int row = idx >> 4, seg = idx & 15;
            *(float4*)&xs[row][seg * 4] =
                *(const float4*)(x + (size_t)(cc * CHUNK + k0 + row) * HID + vb + seg * 4);
        }
        __syncthreads();
#pragma unroll
        for (int kk = 0; kk < 32; kk++) {
            float a[8], b[4];
            *(float4*)&a[0] = *(float4*)&kds[kk][ty * 8];
            *(float4*)&a[4] = *(float4*)&kds[kk][ty * 8 + 4];
            *(float4*)&b[0] = *(float4*)&xs[kk][tx * 4];
#pragma unroll
            for (int i = 0; i < 8; i++)
#pragma unroll
                for (int j = 0; j < 4; j++) acc[i][j] = fmaf(a[i], b[j], acc[i][j]);
        }
        __syncthreads();
    }
    float* T = g_T + (size_t)cc * DK * HID;
#pragma unroll
    for (int i = 0; i < 8; i++) {
        float4 o4 = make_float4(acc[i][0], acc[i][1], acc[i][2], acc[i][3]);
        *(float4*)(T + (size_t)(ty * 8 + i) * HID + vb + tx * 4) = o4;
    }
}

// ---------------- chunk-state scan: in-place T -> S_before --------------------
__global__ void scan_k()
{
    int gid = blockIdx.x * blockDim.x + threadIdx.x;   // 131072 threads
    int vg = gid & 511;
    int rest = gid >> 9;
    int d = rest & 127;
    int b = rest >> 7;
    float4 s = make_float4(0.f, 0.f, 0.f, 0.f);
    for (int c = 0; c < NCHUNK; c++) {
        int cc = b * NCHUNK + c;
        float e = g_el[cc * DK + d];
        float4* p = (float4*)&g_T[((size_t)cc * DK + d) * HID + vg * 4];
        float4 t = *p;
        *p = s;                                        // S before chunk c
        s.x = fmaf(s.x, e, t.x);
        s.y = fmaf(s.y, e, t.y);
        s.z = fmaf(s.z, e, t.z);
        s.w = fmaf(s.w, e, t.w);
    }
}

// ---------------- o = A @ v + qb @ S_before (64x2048 per chunk) ---------------
// Writes o fp32 + single fp16 (A operand of the gate GEMM).
__global__ __launch_bounds__(256) void o_gemm(const float* __restrict__ x)
{
    int cc = blockIdx.y;
    int vb = blockIdx.x * 64;
    int tid = threadIdx.x, tx = tid & 15, ty = tid >> 4;
    __shared__ float Ls[64][33];
    __shared__ float Rs[32][65];
    float acc[4][4] = {};

    for (int ph = 0; ph < 2; ph++) {
        int KK = ph ? DK : CHUNK;
        const float* L = ph ? (g_qb + (size_t)cc * CHUNK * DK)
                            : (g_A + (size_t)cc * CHUNK * CHUNK);
        int lstride = ph ? DK : CHUNK;
        for (int k0 = 0; k0 < KK; k0 += 32) {
#pragma unroll
            for (int rr = 0; rr < 8; rr++) {          // LHS tile 64x32
                int idx = tid + 256 * rr;
                int row = idx >> 5, kk = idx & 31;
                Ls[row][kk] = L[(size_t)row * lstride + k0 + kk];
            }
#pragma unroll
            for (int rr = 0; rr < 8; rr++) {          // RHS tile 32x64
                int idx = tid + 256 * rr;
                int kk = idx >> 6, v = idx & 63;
                float val;
                if (ph == 0)
                    val = x[(size_t)(cc * CHUNK + k0 + kk) * HID + vb + v];
                else
                    val = g_T[(size_t)cc * DK * HID + (size_t)(k0 + kk) * HID + vb + v];
                Rs[kk][v] = val;
            }
            __syncthreads();
#pragma unroll
            for (int kk = 0; kk < 32; kk++) {
                float a[4], b[4];
#pragma unroll
                for (int i = 0; i < 4; i++) a[i] = Ls[ty * 4 + i][kk];
#pragma unroll
                for (int j = 0; j < 4; j++) b[j] = Rs[kk][tx * 4 + j];
#pragma unroll
                for (int i = 0; i < 4; i++)
#pragma unroll
                    for (int j = 0; j < 4; j++) acc[i][j] = fmaf(a[i], b[j], acc[i][j]);
            }
            __syncthreads();
        }
    }
#pragma unroll
    for (int i = 0; i < 4; i++) {
        size_t rowel = (size_t)(cc * CHUNK + ty * 4 + i) * HID + vb + tx * 4;
        float4 v = make_float4(acc[i][0], acc[i][1], acc[i][2], acc[i][3]);
        *(float4*)&g_o[rowel] = v;
        *(__half2*)&g_ohf[rowel]     = __floats2half2_rn(v.x, v.y);
        *(__half2*)&g_ohf[rowel + 2] = __floats2half2_rn(v.z, v.w);
    }
}

// ---------------- t = rmsnorm(o)*gw * silu(G) -> fp16 -------------------------
__global__ __launch_bounds__(256) void gate_norm(const float* __restrict__ o,
                                                 const float* __restrict__ G,
                                                 const float* __restrict__ gw,
                                                 __half* __restrict__ th)
{
    int t = blockIdx.x, tid = threadIdx.x;
    int lane = tid & 31, w = tid >> 5;
    const float2* o2 = (const float2*)(o + (size_t)t * HID);
    const float2* G2 = (const float2*)(G + (size_t)t * HID);
    const float2* w2 = (const float2*)gw;
    float s = 0.f;
    float2 ovs[4];
#pragma unroll
    for (int j = 0; j < 4; j++) {
        ovs[j] = o2[tid + j * 256];
        s = fmaf(ovs[j].x, ovs[j].x, s); s = fmaf(ovs[j].y, ovs[j].y, s);
    }
#pragma unroll
    for (int off = 16; off; off >>= 1) s += __shfl_xor_sync(0xffffffffu, s, off);
    __shared__ float red[8];
    if (!lane) red[w] = s;
    __syncthreads();
    float tot = 0.f;
#pragma unroll
    for (int i = 0; i < 8; i++) tot += red[i];
    float rr = rsqrtf(tot * (1.0f / HID) + 1e-5f);
    __half2* th2 = (__half2*)(th + (size_t)t * HID);
#pragma unroll
    for (int j = 0; j < 4; j++) {
        int idx = tid + j * 256;
        float2 gv = G2[idx], wv = w2[idx];
        float t0 = ovs[j].x * rr * wv.x * (gv.x / (1.f + expf(-gv.x)));
        float t1 = ovs[j].y * rr * wv.y * (gv.y / (1.f + expf(-gv.y)));
        th2[idx] = __floats2half2_rn(t0, t1);
    }
}

// ---------------- launch ------------------------------------------------------
extern "C" void kernel_launch(void* const* d_in, const int* in_sizes, int n_in,
                              void* d_out, int out_size)
{
    const float* x   = (const float*)d_in[0];
    const float* Wq  = (const float*)d_in[1];
    const float* Wk  = (const float*)d_in[2];
    const float* Wog = (const float*)d_in[3];
    const float* Wig = (const float*)d_in[4];
    const float* Wo  = (const float*)d_in[5];
    const float* gw  = (const float*)d_in[6];
    float* out = (float*)d_out;

    float *sq, *sk, *o_, *G;
    cudaGetSymbolAddress((void**)&sq, g_sq);
    cudaGetSymbolAddress((void**)&sk, g_sk);
    cudaGetSymbolAddress((void**)&o_, g_o);
    cudaGetSymbolAddress((void**)&G,  g_G);
    __half *xh, *wq0, *wq1, *wk0, *wk1, *wogh, *wigh, *woh, *ohf, *thf;
    cudaGetSymbolAddress((void**)&xh, g_xh);
    cudaGetSymbolAddress((void**)&wq0, g_wq0); cudaGetSymbolAddress((void**)&wq1, g_wq1);
    cudaGetSymbolAddress((void**)&wk0, g_wk0); cudaGetSymbolAddress((void**)&wk1, g_wk1);
    cudaGetSymbolAddress((void**)&wogh, g_wogh);
    cudaGetSymbolAddress((void**)&wigh, g_wigh);
    cudaGetSymbolAddress((void**)&woh, g_woh);
    cudaGetSymbolAddress((void**)&ohf, g_ohf);
    cudaGetSymbolAddress((void**)&thf, g_thf);

    cudaFuncSetAttribute(tm_gemm, cudaFuncAttributeMaxDynamicSharedMemorySize, GSMEM);

    const int XN4 = NTOK * HID / 4, WN4 = HID * HID / 4, PN4 = DK * HID / 4;

    // 0. x, Wog/Wig/Wo -> fp16 single (x via slot 0; big weights in one launch)
    cvt_h1<<<dim3(XN4 / 256, 1), 256>>>(
        (const float4*)x, (__half2*)xh,
        (const float4*)x, (__half2*)xh,
        (const float4*)x, (__half2*)xh, XN4);
    cvt_h1<<<dim3(WN4 / 256, 3), 256>>>(
        (const float4*)Wog, (__half2*)wogh,
        (const float4*)Wig, (__half2*)wigh,
        (const float4*)Wo,  (__half2*)woh, WN4);
    // 1. Wq, Wk -> fp16 two-level (k feeds the decay cumsum; keep compensated)
    cvt_h2<<<dim3(PN4 / 256, 2), 256>>>(
        (const float4*)Wq, (__half2*)wq0, (__half2*)wq1,
        (const float4*)Wk, (__half2*)wk0, (__half2*)wk1, PN4);

    // 2. q,k projections fused (z selects {Wq0,Wq1}->sq vs {Wk0,Wk1}->sk)
    tm_gemm<<<dim3(1, NTOK / 128, 2), 256, GSMEM>>>(
        xh, xh, xh, xh,
        wq0, wq1, wk0, wk1,
        sq, sk, 2, 1, HID, DK);
    // 3. softmax / sigmoid
    qk_act<<<NTOK, DK>>>(sq, sk);
    // 4. per-chunk decay factors
    chunk_prep<<<NCC, DK>>>(sq, sk);
    // 5. intra-chunk matrices
    a_gemm<<<NCC, 256>>>();
    // 6. per-chunk state contributions T_c
    t_gemm<<<dim3(HID / 64, NCC), 256>>>(x);
    // 7. recurrent scan (in-place: T -> S_before)
    scan_k<<<512, 256>>>();
    // 8. o = A@v + qb@S_before (+ fp16 epilogue)
    o_gemm<<<dim3(HID / 64, NCC), 256>>>(x);
    // 9. gates: G = o@Wog^T + x@Wig^T, 2 single-fp16 phases (one launch)
    tm_gemm<<<dim3(HID / 128, NTOK / 128, 1), 256, GSMEM>>>(
        ohf, xh, xh, xh,
        wogh, wigh, wigh, wigh,
        G, G, 2, 0, HID, HID);
    // 10. rmsnorm + silu gating -> t fp16
    gate_norm<<<NTOK, 256>>>(o_, G, gw, thf);
    // 11. final projection: out = t @ Wo^T, 1 fp16 phase
    tm_gemm<<<dim3(HID / 128, NTOK / 128, 1), 256, GSMEM>>>(
        thf, thf, thf, thf,
        woh, woh, woh, woh,
        out, out, 1, 0, HID, HID);
}

// round 14
// speedup vs baseline: 9.7457x; 1.6244x over previous
#include <cuda_runtime.h>
#include <cuda_fp16.h>
#include <cstdint>
#include <math.h>

// Problem constants
#define BATCH 2
#define SEQ   4096
#define HID   2048
#define DK    128
#define CHUNK 64
#define NCHUNK 64                  // per batch
#define NCC   (BATCH*NCHUNK)       // 128 total batch-chunks
#define NTOK  (BATCH*SEQ)          // 8192

// ---------------- fp32 scratch ------------------------------------------------
__device__ float g_sq[(size_t)NTOK*DK];         // q scores -> q (softmax)
__device__ float g_sk[(size_t)NTOK*DK];         // k scores -> k (sigmoid)
__device__ float g_QE[(size_t)NCC*CHUNK*DK];    // q * exp(B - Bm)
__device__ float g_KE[(size_t)NCC*CHUNK*DK];    // k * exp(Bm - B)
__device__ float g_el[NCC*DK];                  // exp(Blast)
__device__ float g_T [(size_t)NCC*DK*HID];      // T_c (fp32, from tensor t_gemm)
__device__ float g_o [(size_t)NTOK*HID];        // attention output o (fp32)
__device__ float g_G [(size_t)NTOK*HID];        // gate scores

// ---------------- fp16 operand scratch ------------------------------------------
__device__ __align__(16) __half g_xh  [(size_t)NTOK*HID];   // x fp16
__device__ __align__(16) __half g_wq0 [(size_t)DK*HID];
__device__ __align__(16) __half g_wq1 [(size_t)DK*HID];
__device__ __align__(16) __half g_wk0 [(size_t)DK*HID];
__device__ __align__(16) __half g_wk1 [(size_t)DK*HID];
__device__ __align__(16) __half g_wogh[(size_t)HID*HID];
__device__ __align__(16) __half g_wigh[(size_t)HID*HID];
__device__ __align__(16) __half g_woh [(size_t)HID*HID];
__device__ __align__(16) __half g_ohf [(size_t)NTOK*HID];
__device__ __align__(16) __half g_thf [(size_t)NTOK*HID];
// attention mid-section fp16 operands
__device__ __align__(16) __half g_kdT [(size_t)NCC*DK*CHUNK];   // kd^T [cc][d][i]
__device__ __align__(16) __half g_qbh [(size_t)NCC*CHUNK*DK];   // qb   [cc][i][d]
__device__ __align__(16) __half g_Ah  [(size_t)NCC*CHUNK*CHUNK];// A    [cc][i][j]
__device__ __align__(16) __half g_Sh  [(size_t)NCC*DK*HID];     // S_before fp16

// ---------------- helpers -----------------------------------------------------
__device__ __forceinline__ uint32_t smem_u32(const void* p) {
    uint32_t a;
    asm("{ .reg .u64 t; cvta.to.shared.u64 t, %1; cvt.u32.u64 %0, t; }" : "=r"(a) : "l"(p));
    return a;
}
#define CPASYNC16(dst, src) \
    asm volatile("cp.async.cg.shared.global [%0], [%1], 16;" :: "r"(dst), "l"(src) : "memory")
#define CPCOMMIT() asm volatile("cp.async.commit_group;" ::: "memory")
#define CPWAIT1()  asm volatile("cp.async.wait_group 1;" ::: "memory")
#define CPWAIT0()  asm volatile("cp.async.wait_group 0;" ::: "memory")
#define LDSM4(r0, r1, r2, r3, addr) \
    asm volatile("ldmatrix.sync.aligned.m8n8.x4.shared.b16 {%0,%1,%2,%3}, [%4];" \
        : "=r"(r0), "=r"(r1), "=r"(r2), "=r"(r3) : "r"(addr))
#define LDSM4T(r0, r1, r2, r3, addr) \
    asm volatile("ldmatrix.sync.aligned.m8n8.x4.trans.shared.b16 {%0,%1,%2,%3}, [%4];" \
        : "=r"(r0), "=r"(r1), "=r"(r2), "=r"(r3) : "r"(addr))

__device__ __forceinline__ void mma16h(float* c, const uint32_t* a, const uint32_t* b) {
    asm volatile(
        "mma.sync.aligned.m16n8k16.row.col.f32.f16.f16.f32 "
        "{%0,%1,%2,%3}, {%4,%5,%6,%7}, {%8,%9}, {%0,%1,%2,%3};"
        : "+f"(c[0]), "+f"(c[1]), "+f"(c[2]), "+f"(c[3])
        : "r"(a[0]), "r"(a[1]), "r"(a[2]), "r"(a[3]), "r"(b[0]), "r"(b[1]));
}

// ---------------- fp32 -> fp16 single conversion (up to 3 tensors) -------------
__global__ void cvt_h1(const float4* __restrict__ s0, __half2* d0o,
                       const float4* __restrict__ s1, __half2* d1o,
                       const float4* __restrict__ s2, __half2* d2o, int n4)
{
    const float4* src; __half2* dst;
    if (blockIdx.y == 0)      { src = s0; dst = d0o; }
    else if (blockIdx.y == 1) { src = s1; dst = d1o; }
    else                      { src = s2; dst = d2o; }
    int i = blockIdx.x * blockDim.x + threadIdx.x;
    if (i >= n4) return;
    float4 v = src[i];
    dst[2 * i]     = __floats2half2_rn(v.x, v.y);
    dst[2 * i + 1] = __floats2half2_rn(v.z, v.w);
}

// ---------------- fp32 -> fp16 two-level split (up to 2 tensors) ---------------
__global__ void cvt_h2(const float4* __restrict__ s0, __half2* h00, __half2* h01,
                       const float4* __restrict__ s1, __half2* h10, __half2* h11,
                       int n4)
{
    const float4* src; __half2 *d0, *d1;
    if (blockIdx.y == 0) { src = s0; d0 = h00; d1 = h01; }
    else                 { src = s1; d0 = h10; d1 = h11; }
    int i = blockIdx.x * blockDim.x + threadIdx.x;
    if (i >= n4) return;
    float4 v = src[i];
    __half a0 = __float2half_rn(v.x), a1 = __float2half_rn(v.y);
    __half a2 = __float2half_rn(v.z), a3 = __float2half_rn(v.w);
    d0[2 * i]     = __halves2half2(a0, a1);
    d0[2 * i + 1] = __halves2half2(a2, a3);
    d1[2 * i]     = __floats2half2_rn(v.x - __half2float(a0), v.y - __half2float(a1));
    d1[2 * i + 1] = __floats2half2_rn(v.z - __half2float(a2), v.w - __half2float(a3));
}

// ============ fp16 mma.sync GEMM: C[M,Ncols] = sum_ph A_ph[M,K]@B_ph[n,K]^T ====
#define KC 64
#define PITCHB 144                 // bytes per smem row (64 fp16 + 16B pad)
#define TILEB (128 * PITCHB)       // 18432
#define STAGEB (2 * TILEB)         // 36864 (A tile + B tile)
#define NSTG 3
#define GSMEM (NSTG * STAGEB)      // 110592

__global__ void __launch_bounds__(256, 2) tm_gemm(
    const __half* __restrict__ A0, const __half* __restrict__ A1,
    const __half* __restrict__ A2, const __half* __restrict__ A3,
    const __half* __restrict__ B0, const __half* __restrict__ B1,
    const __half* __restrict__ B2, const __half* __restrict__ B3,
    float* __restrict__ C0, float* __restrict__ C1,
    int nphase, int zsplit, int K, int Ncols)
{
    extern __shared__ char smc[];
    const int tid = threadIdx.x, lane = tid & 31, wid = tid >> 5;
    const int wm = wid & 1, wn = wid >> 1;
    const int r = lane >> 2, kq = lane & 3;
    const long bm = (long)blockIdx.y * 128;
    const long bn = (long)blockIdx.x * 128;

    int pbeg = 0, pcnt = nphase;
    float* C = C0;
    if (zsplit) { pcnt = 2; if (blockIdx.z) { pbeg = 2; C = C1; } }
    const int nT = pcnt * 32;            // K == 2048 -> 32 chunks per phase

    float acc[4][4][4];
#pragma unroll
    for (int i = 0; i < 4; i++)
#pragma unroll
        for (int j = 0; j < 4; j++)
#pragma unroll
            for (int t = 0; t < 4; t++) acc[i][j][t] = 0.f;

    const uint32_t sb = smem_u32(smc);

    auto getAB = [&](int t, const __half*& a, const __half*& b, int& k0) {
        int ph = pbeg + (t >> 5);
        k0 = (t & 31) * KC;
        switch (ph) {
            case 0: a = A0; b = B0; break;
            case 1: a = A1; b = B1; break;
            case 2: a = A2; b = B2; break;
            default: a = A3; b = B3; break;
        }
    };

    auto issue = [&](int t, int stg) {
        const __half *Ap, *Bp; int k0;
        getAB(t, Ap, Bp, k0);
        uint32_t As = sb + stg * STAGEB;
        uint32_t Bs = As + TILEB;
#pragma unroll
        for (int i = 0; i < 4; i++) {
            int u = tid + i * 256;
            int row = u >> 3, s = u & 7;
            CPASYNC16(As + row * PITCHB + s * 16, Ap + (bm + row) * (long)K + k0 + s * 8);
            CPASYNC16(Bs + row * PITCHB + s * 16, Bp + (bn + row) * (long)K + k0 + s * 8);
        }
        CPCOMMIT();
    };

    const int lm = lane >> 3, li = lane & 7;
    uint32_t aoff[4], boff[2];
#pragma unroll
    for (int mt = 0; mt < 4; mt++) {
        int arow = wm * 64 + mt * 16 + (lm & 1) * 8 + li;
        aoff[mt] = (uint32_t)(arow * PITCHB + (lm >> 1) * 16);
    }
#pragma unroll
    for (int p = 0; p < 2; p++) {
        int nt = 2 * p + (lm >> 1);
        int brow = wn * 32 + nt * 8 + li;
        boff[p] = (uint32_t)(brow * PITCHB + (lm & 1) * 16);
    }

    issue(0, 0);
    if (nT > 1) issue(1, 1);

    int st = 0, ist = 2;
    for (int t = 0; t < nT; t++) {
        if (t == nT - 1) CPWAIT0(); else CPWAIT1();
        __syncthreads();
        if (t + 2 < nT) issue(t + 2, ist);
        uint32_t As = sb + st * STAGEB;
        uint32_t Bs = As + TILEB;
#pragma unroll
        for (int ks = 0; ks < 4; ks++) {
            uint32_t af[4][4], bfr[2][4];
#pragma unroll
            for (int mt = 0; mt < 4; mt++)
                LDSM4(af[mt][0], af[mt][1], af[mt][2], af[mt][3], As + aoff[mt] + ks * 32);
#pragma unroll
            for (int p = 0; p < 2; p++)
                LDSM4(bfr[p][0], bfr[p][1], bfr[p][2], bfr[p][3], Bs + boff[p] + ks * 32);
#pragma unroll
            for (int mt = 0; mt < 4; mt++) {
                mma16h(acc[mt][0], af[mt], &bfr[0][0]);
                mma16h(acc[mt][1], af[mt], &bfr[0][2]);
                mma16h(acc[mt][2], af[mt], &bfr[1][0]);
                mma16h(acc[mt][3], af[mt], &bfr[1][2]);
            }
        }
        st = (st == NSTG - 1) ? 0 : st + 1;
        ist = (ist == NSTG - 1) ? 0 : ist + 1;
    }

#pragma unroll
    for (int mt = 0; mt < 4; mt++) {
        long row = bm + wm * 64 + mt * 16 + r;
#pragma unroll
        for (int nt = 0; nt < 4; nt++) {
            long col = bn + wn * 32 + nt * 8 + kq * 2;
            *(float2*)&C[row * (long)Ncols + col] =
                make_float2(acc[mt][nt][0], acc[mt][nt][1]);
            *(float2*)&C[(row + 8) * (long)Ncols + col] =
                make_float2(acc[mt][nt][2], acc[mt][nt][3]);
        }
    }
}

// ============ tensor t_gemm: T_c[128,128vb] = kdT[128,64] @ x[64,128vb] ========
// A = kdT (K-major, 64 halves/row); B = x rows (trans-loaded).
#define TA_PITCH 144               // 64 halves + pad
#define TB_PITCH 272               // 128 halves + pad
#define TGA (128 * TA_PITCH)       // 18432
#define TGB (64 * TB_PITCH)        // 17408
#define TG_SMEM (TGA + TGB)        // 35840

__global__ void __launch_bounds__(256, 2) t_gemm_h(const __half* __restrict__ xh)
{
    extern __shared__ char smc[];
    const int cc = blockIdx.y;
    const int vb = blockIdx.x * 128;
    const int tid = threadIdx.x, lane = tid & 31, wid = tid >> 5;
    const int wm = wid & 1, wn = wid >> 1;
    const int r = lane >> 2, kq = lane & 3;
    const int lm = lane >> 3, li = lane & 7;
    const uint32_t As = smem_u32(smc);
    const uint32_t Bs = As + TGA;

    const __half* kdT = g_kdT + (size_t)cc * DK * CHUNK;
    // stage A: 128 rows x 128B
#pragma unroll
    for (int j = 0; j < 4; j++) {
        int u = tid + j * 256;
        int row = u >> 3, s = u & 7;
        CPASYNC16(As + row * TA_PITCH + s * 16, kdT + row * CHUNK + s * 8);
    }
    // stage B: 64 rows x 256B from x rows of this chunk
#pragma unroll
    for (int j = 0; j < 4; j++) {
        int u = tid + j * 256;
        int row = u >> 4, s = u & 15;
        CPASYNC16(Bs + row * TB_PITCH + s * 16,
                  xh + (size_t)(cc * CHUNK + row) * HID + vb + s * 8);
    }
    CPCOMMIT(); CPWAIT0();
    __syncthreads();

    float acc[4][4][4];
#pragma unroll
    for (int i = 0; i < 4; i++)
#pragma unroll
        for (int j = 0; j < 4; j++)
#pragma unroll
            for (int t = 0; t < 4; t++) acc[i][j][t] = 0.f;

#pragma unroll
    for (int ks = 0; ks < 4; ks++) {
        uint32_t af[4][4], bfr[2][4];
#pragma unroll
        for (int mt = 0; mt < 4; mt++) {
            int arow = wm * 64 + mt * 16 + (lm & 1) * 8 + li;
            LDSM4(af[mt][0], af[mt][1], af[mt][2], af[mt][3],
                  As + arow * TA_PITCH + (lm >> 1) * 16 + ks * 32);
        }
#pragma unroll
        for (int p = 0; p < 2; p++) {
            int krow = ks * 16 + (lm & 1) * 8 + li;
            int ncol = wn * 32 + (2 * p + (lm >> 1)) * 8;
            LDSM4T(bfr[p][0], bfr[p][1], bfr[p][2], bfr[p][3],
                   Bs + krow * TB_PITCH + ncol * 2);
        }
#pragma unroll
        for (int mt = 0; mt < 4; mt++) {
            mma16h(acc[mt][0], af[mt], &bfr[0][0]);
            mma16h(acc[mt][1], af[mt], &bfr[0][2]);
            mma16h(acc[mt][2], af[mt], &bfr[1][0]);
            mma16h(acc[mt][3], af[mt], &bfr[1][2]);
        }
    }

    float* T = g_T + (size_t)cc * DK * HID;
#pragma unroll
    for (int mt = 0; mt < 4; mt++) {
        int row = wm * 64 + mt * 16 + r;
#pragma unroll
        for (int nt = 0; nt < 4; nt++) {
            int col = vb + wn * 32 + nt * 8 + kq * 2;
            *(float2*)&T[(size_t)row * HID + col] =
                make_float2(acc[mt][nt][0], acc[mt][nt][1]);
            *(float2*)&T[(size_t)(row + 8) * HID + col] =
                make_float2(acc[mt][nt][2], acc[mt][nt][3]);
        }
    }
}

// ============ tensor o_gemm: o[64,128vb] = A[64,64]@x + qb[64,128]@S ===========
#define OA_OFF 0                       // A:  64 x TA_PITCH  = 9216
#define OQ_OFF (64 * TA_PITCH)         // qb: 64 x TB_PITCH  = 17408
#define OV_OFF (OQ_OFF + 64 * TB_PITCH)   // v: 64 x TB_PITCH
#define OS_OFF (OV_OFF + 64 * TB_PITCH)   // S: 128 x TB_PITCH = 34816
#define OG_SMEM (OS_OFF + 128 * TB_PITCH) // 78848

__global__ void __launch_bounds__(256, 2) o_gemm_h(const __half* __restrict__ xh)
{
    extern __shared__ char smc[];
    const int cc = blockIdx.y;
    const int vb = blockIdx.x * 128;
    const int tid = threadIdx.x, lane = tid & 31, wid = tid >> 5;
    const int wm = wid & 1, wn = wid >> 1;
    const int r = lane >> 2, kq = lane & 3;
    const int lm = lane >> 3, li = lane & 7;
    const uint32_t sb = smem_u32(smc);

    const __half* Ap = g_Ah + (size_t)cc * CHUNK * CHUNK;
    const __half* Qp = g_qbh + (size_t)cc * CHUNK * DK;
    const __half* Sp = g_Sh + (size_t)cc * DK * HID;

    // stage A: 64 x 128B
#pragma unroll
    for (int j = 0; j < 2; j++) {
        int u = tid + j * 256;
        int row = u >> 3, s = u & 7;
        CPASYNC16(sb + OA_OFF + row * TA_PITCH + s * 16, Ap + row * CHUNK + s * 8);
    }
    // stage qb: 64 x 256B
#pragma unroll
    for (int j = 0; j < 4; j++) {
        int u = tid + j * 256;
        int row = u >> 4, s = u & 15;
        CPASYNC16(sb + OQ_OFF + row * TB_PITCH + s * 16, Qp + row * DK + s * 8);
    }
    // stage v: 64 x 256B from x rows
#pragma unroll
    for (int j = 0; j < 4; j++) {
        int u = tid + j * 256;
        int row = u >> 4, s = u & 15;
        CPASYNC16(sb + OV_OFF + row * TB_PITCH + s * 16,
                  xh + (size_t)(cc * CHUNK + row) * HID + vb + s * 8);
    }
    // stage S: 128 x 256B
#pragma unroll
    for (int j = 0; j < 8; j++) {
        int u = tid + j * 256;
        int row = u >> 4, s = u & 15;
        CPASYNC16(sb + OS_OFF + row * TB_PITCH + s * 16,
                  Sp + (size_t)row * HID + vb + s * 8);
    }
    CPCOMMIT(); CPWAIT0();
    __syncthreads();

    float acc[2][4][4];
#pragma unroll
    for (int i = 0; i < 2; i++)
#pragma unroll
        for (int j = 0; j < 4; j++)
#pragma unroll
            for (int t = 0; t < 4; t++) acc[i][j][t] = 0.f;

    // phase A: K=64, A matrix (pitch TA), B = v tile
#pragma unroll
    for (int ks = 0; ks < 4; ks++) {
        uint32_t af[2][4], bfr[2][4];
#pragma unroll
        for (int mt = 0; mt < 2; mt++) {
            int arow = wm * 32 + mt * 16 + (lm & 1) * 8 + li;
            LDSM4(af[mt][0], af[mt][1], af[mt][2], af[mt][3],
                  sb + OA_OFF + arow * TA_PITCH + (lm >> 1) * 16 + ks * 32);
        }
#pragma unroll
        for (int p = 0; p < 2; p++) {
            int krow = ks * 16 + (lm & 1) * 8 + li;
            int ncol = wn * 32 + (2 * p + (lm >> 1)) * 8;
            LDSM4T(bfr[p][0], bfr[p][1], bfr[p][2], bfr[p][3],
                   sb + OV_OFF + krow * TB_PITCH + ncol * 2);
        }
#pragma unroll
        for (int mt = 0; mt < 2; mt++) {
            mma16h(acc[mt][0], af[mt], &bfr[0][0]);
            mma16h(acc[mt][1], af[mt], &bfr[0][2]);
            mma16h(acc[mt][2], af[mt], &bfr[1][0]);
            mma16h(acc[mt][3], af[mt], &bfr[1][2]);
        }
    }
    // phase B: K=128, qb (pitch TB), B = S tile
#pragma unroll
    for (int ks = 0; ks < 8; ks++) {
        uint32_t af[2][4], bfr[2][4];
#pragma unroll
        for (int mt = 0; mt < 2; mt++) {
            int arow = wm * 32 + mt * 16 + (lm & 1) * 8 + li;
            LDSM4(af[mt][0], af[mt][1], af[mt][2], af[mt][3],
                  sb + OQ_OFF + arow * TB_PITCH + (lm >> 1) * 16 + ks * 32);
        }
#pragma unroll
        for (int p = 0; p < 2; p++) {
            int krow = ks * 16 + (lm & 1) * 8 + li;
            int ncol = wn * 32 + (2 * p + (lm >> 1)) * 8;
            LDSM4T(bfr[p][0], bfr[p][1], bfr[p][2], bfr[p][3],
                   sb + OS_OFF + krow * TB_PITCH + ncol * 2);
        }
#pragma unroll
        for (int mt = 0; mt < 2; mt++) {
            mma16h(acc[mt][0], af[mt], &bfr[0][0]);
            mma16h(acc[mt][1], af[mt], &bfr[0][2]);
            mma16h(acc[mt][2], af[mt], &bfr[1][0]);
            mma16h(acc[mt][3], af[mt], &bfr[1][2]);
        }
    }

    // epilogue: fp32 o + fp16 ohf
#pragma unroll
    for (int mt = 0; mt < 2; mt++) {
        size_t row = (size_t)cc * CHUNK + wm * 32 + mt * 16 + r;
#pragma unroll
        for (int nt = 0; nt < 4; nt++) {
            int col = vb + wn * 32 + nt * 8 + kq * 2;
            *(float2*)&g_o[row * HID + col] =
                make_float2(acc[mt][nt][0], acc[mt][nt][1]);
            *(float2*)&g_o[(row + 8) * HID + col] =
                make_float2(acc[mt][nt][2], acc[mt][nt][3]);
            *(__half2*)&g_ohf[row * HID + col] =
                __floats2half2_rn(acc[mt][nt][0], acc[mt][nt][1]);
            *(__half2*)&g_ohf[(row + 8) * HID + col] =
                __floats2half2_rn(acc[mt][nt][2], acc[mt][nt][3]);
        }
    }
}

// ---------------- q softmax / k sigmoid (in-place on score buffers) -----------
__global__ void qk_act(float* __restrict__ sq, float* __restrict__ sk)
{
    int t = blockIdx.x, d = threadIdx.x;            // 128 threads
    int lane = d & 31, w = d >> 5;
    __shared__ float sm[4], ss[4];
    size_t idx = (size_t)t * DK + d;
    float v = sq[idx];
    float m = v;
#pragma unroll
    for (int o = 16; o; o >>= 1) m = fmaxf(m, __shfl_xor_sync(0xffffffffu, m, o));
    if (!lane) sm[w] = m;
    __syncthreads();
    m = fmaxf(fmaxf(sm[0], sm[1]), fmaxf(sm[2], sm[3]));
    float e = expf(v - m);
    float s = e;
#pragma unroll
    for (int o = 16; o; o >>= 1) s += __shfl_xor_sync(0xffffffffu, s, o);
    if (!lane) ss[w] = s;
    __syncthreads();
    s = ss[0] + ss[1] + ss[2] + ss[3];
    sq[idx] = e / s;
    float kv = sk[idx];
    sk[idx] = 1.f / (1.f + expf(-kv));
}

// ---------------- per-chunk decay prep (product form) -------------------------
// Emits fp32 QE/KE (a_gemm) and fp16 kdT [d][i] / qb [i][d] (tensor kernels).
__global__ void chunk_prep(const float* __restrict__ q, const float* __restrict__ k)
{
    int cc = blockIdx.x;
    int d = threadIdx.x;                 // 128 threads
    __shared__ float us[CHUNK][DK];
    size_t base = (size_t)cc * CHUNK * DK + d;
    float P = 1.f;
#pragma unroll 4
    for (int i = 0; i < CHUNK; i++) {
        float kv = k[base + (size_t)i * DK];
        float u = 1.f / (1.f + expf(kv));
        us[i][d] = u;
        P *= u;
    }
    float Pl = P;
    float invs = rsqrtf(Pl);
    float sq_ = sqrtf(Pl);
    __half* kdT = g_kdT + (size_t)cc * DK * CHUNK + (size_t)d * CHUNK;
    __half* qbh = g_qbh + (size_t)cc * CHUNK * DK + d;
    P = 1.f;
#pragma unroll 4
    for (int i = 0; i < CHUNK; i++) {
        size_t idx = base + (size_t)i * DK;
        P *= us[i][d];
        float qv = q[idx];
        float kv = k[idx];
        g_QE[idx] = qv * (P * invs);
        g_KE[idx] = kv * (sq_ / P);
        qbh[(size_t)i * DK] = __float2half_rn(qv * P);
        kdT[i] = __float2half_rn(kv * (Pl / P));
    }
    g_el[cc * DK + d] = Pl;
}

// ---------------- A = tril(QE @ KE^T) per chunk (64x64, K=128) -> fp16 --------
__global__ __launch_bounds__(256) void a_gemm()
{
    int cc = blockIdx.x;
    int tid = threadIdx.x, tx = tid & 15, ty = tid >> 4;
    __shared__ float Qs[64][33];
    __shared__ float Ks[64][33];
    float acc[4][4] = {};
    const float* Q  = g_QE + (size_t)cc * CHUNK * DK;
    const float* Kp = g_KE + (size_t)cc * CHUNK * DK;
    for (int k0 = 0; k0 < DK; k0 += 32) {
#pragma unroll
        for (int rr = 0; rr < 8; rr++) {
            int idx = tid + 256 * rr;
            int row = idx >> 5, kk = idx & 31;
            Qs[row][kk] = Q [row * DK + k0 + kk];
            Ks[row][kk] = Kp[row * DK + k0 + kk];
        }
        __syncthreads();
#pragma unroll
        for (int kk = 0; kk < 32; kk++) {
            float a[4], b[4];
#pragma unroll
            for (int i = 0; i < 4; i++) a[i] = Qs[ty * 4 + i][kk];
#pragma unroll
            for (int j = 0; j < 4; j++) b[j] = Ks[tx * 4 + j][kk];
#pragma unroll
            for (int i = 0; i < 4; i++)
#pragma unroll
                for (int j = 0; j < 4; j++) acc[i][j] = fmaf(a[i], b[j], acc[i][j]);
        }
        __syncthreads();
    }
#pragma unroll
    for (int i = 0; i < 4; i++) {
        int I = ty * 4 + i, J = tx * 4;
        float v0 = (J     <= I) ? acc[i][0] : 0.f;
        float v1 = (J + 1 <= I) ? acc[i][1] : 0.f;
        float v2 = (J + 2 <= I) ? acc[i][2] : 0.f;
        float v3 = (J + 3 <= I) ? acc[i][3] : 0.f;
        __half2* dst = (__half2*)&g_Ah[(size_t)cc * CHUNK * CHUNK + I * CHUNK + J];
        dst[0] = __floats2half2_rn(v0, v1);
        dst[1] = __floats2half2_rn(v2, v3);
    }
}

// ---------------- chunk-state scan: read fp32 T, write fp16 S_before ----------
__global__ void scan_k()
{
    int gid = blockIdx.x * blockDim.x + threadIdx.x;   // 131072 threads
    int vg = gid & 511;
    int rest = gid >> 9;
    int d = rest & 127;
    int b = rest >> 7;
    float4 s = make_float4(0.f, 0.f, 0.f, 0.f);
    for (int c = 0; c < NCHUNK; c++) {
        int cc = b * NCHUNK + c;
        float e = g_el[cc * DK + d];
        size_t off = ((size_t)cc * DK + d) * HID + vg * 4;
        float4 t = *(const float4*)&g_T[off];
        __half2* sh = (__half2*)&g_Sh[off];
        sh[0] = __floats2half2_rn(s.x, s.y);               // S before chunk c
        sh[1] = __floats2half2_rn(s.z, s.w);
        s.x = fmaf(s.x, e, t.x);
        s.y = fmaf(s.y, e, t.y);
        s.z = fmaf(s.z, e, t.z);
        s.w = fmaf(s.w, e, t.w);
    }
}

// ---------------- t = rmsnorm(o)*gw * silu(G) -> fp16 -------------------------
__global__ __launch_bounds__(256) void gate_norm(const float* __restrict__ o,
                                                 const float* __restrict__ G,
                                                 const float* __restrict__ gw,
                                                 __half* __restrict__ th)
{
    int t = blockIdx.x, tid = threadIdx.x;
    int lane = tid & 31, w = tid >> 5;
    const float2* o2 = (const float2*)(o + (size_t)t * HID);
    const float2* G2 = (const float2*)(G + (size_t)t * HID);
    const float2* w2 = (const float2*)gw;
    float s = 0.f;
    float2 ovs[4];
#pragma unroll
    for (int j = 0; j < 4; j++) {
        ovs[j] = o2[tid + j * 256];
        s = fmaf(ovs[j].x, ovs[j].x, s); s = fmaf(ovs[j].y, ovs[j].y, s);
    }
#pragma unroll
    for (int off = 16; off; off >>= 1) s += __shfl_xor_sync(0xffffffffu, s, off);
    __shared__ float red[8];
    if (!lane) red[w] = s;
    __syncthreads();
    float tot = 0.f;
#pragma unroll
    for (int i = 0; i < 8; i++) tot += red[i];
    float rr = rsqrtf(tot * (1.0f / HID) + 1e-5f);
    __half2* th2 = (__half2*)(th + (size_t)t * HID);
#pragma unroll
    for (int j = 0; j < 4; j++) {
        int idx = tid + j * 256;
        float2 gv = G2[idx], wv = w2[idx];
        float t0 = ovs[j].x * rr * wv.x * (gv.x / (1.f + expf(-gv.x)));
        float t1 = ovs[j].y * rr * wv.y * (gv.y / (1.f + expf(-gv.y)));
        th2[idx] = __floats2half2_rn(t0, t1);
    }
}

// ---------------- launch ------------------------------------------------------
extern "C" void kernel_launch(void* const* d_in, const int* in_sizes, int n_in,
                              void* d_out, int out_size)
{
    const float* x   = (const float*)d_in[0];
    const float* Wq  = (const float*)d_in[1];
    const float* Wk  = (const float*)d_in[2];
    const float* Wog = (const float*)d_in[3];
    const float* Wig = (const float*)d_in[4];
    const float* Wo  = (const float*)d_in[5];
    const float* gw  = (const float*)d_in[6];
    float* out = (float*)d_out;

    float *sq, *sk, *o_, *G;
    cudaGetSymbolAddress((void**)&sq, g_sq);
    cudaGetSymbolAddress((void**)&sk, g_sk);
    cudaGetSymbolAddress((void**)&o_, g_o);
    cudaGetSymbolAddress((void**)&G,  g_G);
    __half *xh, *wq0, *wq1, *wk0, *wk1, *wogh, *wigh, *woh, *ohf, *thf;
    cudaGetSymbolAddress((void**)&xh, g_xh);
    cudaGetSymbolAddress((void**)&wq0, g_wq0); cudaGetSymbolAddress((void**)&wq1, g_wq1);
    cudaGetSymbolAddress((void**)&wk0, g_wk0); cudaGetSymbolAddress((void**)&wk1, g_wk1);
    cudaGetSymbolAddress((void**)&wogh, g_wogh);
    cudaGetSymbolAddress((void**)&wigh, g_wigh);
    cudaGetSymbolAddress((void**)&woh, g_woh);
    cudaGetSymbolAddress((void**)&ohf, g_ohf);
    cudaGetSymbolAddress((void**)&thf, g_thf);

    cudaFuncSetAttribute(tm_gemm, cudaFuncAttributeMaxDynamicSharedMemorySize, GSMEM);
    cudaFuncSetAttribute(t_gemm_h, cudaFuncAttributeMaxDynamicSharedMemorySize, TG_SMEM);
    cudaFuncSetAttribute(o_gemm_h, cudaFuncAttributeMaxDynamicSharedMemorySize, OG_SMEM);

    const int XN4 = NTOK * HID / 4, WN4 = HID * HID / 4, PN4 = DK * HID / 4;

    // 0. x -> fp16; big weights -> fp16 single
    cvt_h1<<<dim3(XN4 / 256, 1), 256>>>(
        (const float4*)x, (__half2*)xh,
        (const float4*)x, (__half2*)xh,
        (const float4*)x, (__half2*)xh, XN4);
    cvt_h1<<<dim3(WN4 / 256, 3), 256>>>(
        (const float4*)Wog, (__half2*)wogh,
        (const float4*)Wig, (__half2*)wigh,
        (const float4*)Wo,  (__half2*)woh, WN4);
    // 1. Wq, Wk -> fp16 two-level (k feeds the decay cumsum; keep compensated)
    cvt_h2<<<dim3(PN4 / 256, 2), 256>>>(
        (const float4*)Wq, (__half2*)wq0, (__half2*)wq1,
        (const float4*)Wk, (__half2*)wk0, (__half2*)wk1, PN4);

    // 2. q,k projections fused
    tm_gemm<<<dim3(1, NTOK / 128, 2), 256, GSMEM>>>(
        xh, xh, xh, xh,
        wq0, wq1, wk0, wk1,
        sq, sk, 2, 1, HID, DK);
    // 3-4. activations + decay factors
    qk_act<<<NTOK, DK>>>(sq, sk);
    chunk_prep<<<NCC, DK>>>(sq, sk);
    // 5. intra-chunk matrices (fp32 compute, fp16 out)
    a_gemm<<<NCC, 256>>>();
    // 6. T_c = kdT @ v (tensor)
    t_gemm_h<<<dim3(HID / 128, NCC), 256, TG_SMEM>>>(xh);
    // 7. recurrent scan: fp32 T -> fp16 S_before
    scan_k<<<512, 256>>>();
    // 8. o = A@v + qb@S (tensor)
    o_gemm_h<<<dim3(HID / 128, NCC), 256, OG_SMEM>>>(xh);
    // 9. gates: G = o@Wog^T + x@Wig^T
    tm_gemm<<<dim3(HID / 128, NTOK / 128, 1), 256, GSMEM>>>(
        ohf, xh, xh, xh,
        wogh, wigh, wigh, wigh,
        G, G, 2, 0, HID, HID);
    // 10. rmsnorm + silu gating -> t fp16
    gate_norm<<<NTOK, 256>>>(o_, G, gw, thf);
    // 11. final projection
    tm_gemm<<<dim3(HID / 128, NTOK / 128, 1), 256, GSMEM>>>(
        thf, thf, thf, thf,
        woh, woh, woh, woh,
        out, out, 1, 0, HID, HID);
}